// round 7
// baseline (speedup 1.0000x reference)
#include <cuda_runtime.h>
#include <math.h>
#include <stdint.h>

#define CIN   128
#define COUTB 256
#define HW    384
#define LPOS  16384            // (384/3)^2 patches
#define NB    4

// ---------------- scratch (static __device__; no allocations allowed) ----------------
// y layout: [b*9+k][p][c]  (c innermost -> GEMM reads rows of channels, coalesced)
__device__ float g_y1[(size_t)NB * 9 * LPOS * CIN];     // 302 MB
__device__ float g_y2[(size_t)NB * 9 * LPOS * COUTB];   // 604 MB
// split-K partials: [(bk*2+mt)*16+s][o 128][i 128]
__device__ float g_part[(size_t)36 * 2 * 16 * 128 * 128];  // 75.5 MB

// ---------------- f32x2 helpers ----------------
__device__ __forceinline__ unsigned long long pack2(float x, float y) {
    unsigned long long r;
    asm("mov.b64 %0, {%1,%2};" : "=l"(r) : "f"(x), "f"(y));
    return r;
}
__device__ __forceinline__ unsigned long long fma2(unsigned long long a,
                                                   unsigned long long b,
                                                   unsigned long long c) {
    unsigned long long d;
    asm("fma.rn.f32x2 %0, %1, %2, %3;" : "=l"(d) : "l"(a), "l"(b), "l"(c));
    return d;
}
__device__ __forceinline__ float2 unpack2(unsigned long long v) {
    float2 f;
    asm("mov.b64 {%0,%1}, %2;" : "=f"(f.x), "=f"(f.y) : "l"(v));
    return f;
}

// =====================================================================
// Conv 3x3 (pad 1) + unfold-bin scatter.
// Tile: 32 couts x (8 rows x 32 cols). 256 threads.
// thread: cogrp = t/64 (8 couts as 4 f32x2 pairs), 4 adjacent pixels.
// =====================================================================
template <int COUT>
__global__ void __launch_bounds__(256, 2)
conv_bin_kernel(const float* __restrict__ x, const float* __restrict__ w)
{
    __shared__ __align__(16) float xs[8 * 10 * 36];   // [ci 8][row 10][col 34 pad 36]
    __shared__ __align__(16) float ws[8 * 9 * 32];    // [ci 8][tap 9][co 32]

    float* __restrict__ ys = (COUT == CIN) ? g_y1 : g_y2;

    const int colBase = blockIdx.x * 32;
    const int rowBase = blockIdx.y * 8;
    const int nct     = COUT / 32;
    const int ct      = blockIdx.z % nct;
    const int b       = blockIdx.z / nct;
    const int co0     = ct * 32;

    const int t     = threadIdx.x;
    const int cogrp = t >> 6;           // 0..3 -> co sub-base cogrp*8
    const int pxg   = t & 63;           // 0..63
    const int r     = pxg >> 3;         // 0..7 local row
    const int c0    = (pxg & 7) * 4;    // local col base (4 px per thread)

    const float* __restrict__ xb = x + (size_t)b * CIN * HW * HW;

    unsigned long long acc[4][4];
#pragma unroll
    for (int j = 0; j < 4; j++)
#pragma unroll
        for (int q = 0; q < 4; q++) acc[j][q] = 0ull;

    for (int ci0 = 0; ci0 < CIN; ci0 += 8) {
        // ---- stage x chunk: 8 ch x 10 x 34 (halo, zero-padded) ----
        for (int e = t; e < 8 * 10 * 34; e += 256) {
            int cc  = e / 340;
            int rem = e - cc * 340;
            int rr  = rem / 34;
            int cl  = rem - rr * 34;
            int gr  = rowBase - 1 + rr;
            int gc  = colBase - 1 + cl;
            float v = 0.f;
            if ((unsigned)gr < HW && (unsigned)gc < HW)
                v = xb[((size_t)(ci0 + cc) * HW + gr) * HW + gc];
            xs[cc * 360 + rr * 36 + cl] = v;
        }
        // ---- stage w chunk: ws[cc][tap][co] ----
        for (int e = t; e < 8 * 9 * 32; e += 256) {
            int cc  = e / 288;
            int rem = e - cc * 288;
            int t9  = rem >> 5;
            int co  = rem & 31;
            ws[cc * 288 + t9 * 32 + co] =
                w[((size_t)(co0 + co) * CIN + (ci0 + cc)) * 9 + t9];
        }
        __syncthreads();

#pragma unroll 2
        for (int cc = 0; cc < 8; cc++) {
            const float* xr = &xs[cc * 360 + r * 36 + c0];
            float xv[3][6];
#pragma unroll
            for (int kh = 0; kh < 3; kh++) {
                float4 v4 = *(const float4*)(xr + kh * 36);
                float2 v2 = *(const float2*)(xr + kh * 36 + 4);
                xv[kh][0] = v4.x; xv[kh][1] = v4.y; xv[kh][2] = v4.z;
                xv[kh][3] = v4.w; xv[kh][4] = v2.x; xv[kh][5] = v2.y;
            }
            // warp-uniform weight pairs (broadcast LDS.64)
            const unsigned long long* wr =
                (const unsigned long long*)&ws[cc * 288 + cogrp * 8];
#pragma unroll
            for (int kh = 0; kh < 3; kh++) {
#pragma unroll
                for (int kw = 0; kw < 3; kw++) {
                    const int t9 = kh * 3 + kw;
                    unsigned long long w0 = wr[t9 * 16 + 0];
                    unsigned long long w1 = wr[t9 * 16 + 1];
                    unsigned long long w2 = wr[t9 * 16 + 2];
                    unsigned long long w3 = wr[t9 * 16 + 3];
#pragma unroll
                    for (int j = 0; j < 4; j++) {
                        unsigned long long xb2 = pack2(xv[kh][kw + j], xv[kh][kw + j]);
                        acc[j][0] = fma2(w0, xb2, acc[j][0]);
                        acc[j][1] = fma2(w1, xb2, acc[j][1]);
                        acc[j][2] = fma2(w2, xb2, acc[j][2]);
                        acc[j][3] = fma2(w3, xb2, acc[j][3]);
                    }
                }
            }
        }
        __syncthreads();
    }

    // ---- epilogue: scatter into bin layout y[(b*9+k)][p][c] ----
    const int h = rowBase + r;
#pragma unroll
    for (int j = 0; j < 4; j++) {
        int wc = colBase + c0 + j;
        int k  = (h % 3) * 3 + (wc % 3);
        int p  = (h / 3) * 128 + (wc / 3);
        float* dst = ys + (((size_t)(b * 9 + k) * LPOS + p) * COUT + co0 + cogrp * 8);
        float2 a0 = unpack2(acc[j][0]);
        float2 a1 = unpack2(acc[j][1]);
        float2 a2 = unpack2(acc[j][2]);
        float2 a3 = unpack2(acc[j][3]);
        *(float4*)dst       = make_float4(a0.x, a0.y, a1.x, a1.y);
        *(float4*)(dst + 4) = make_float4(a2.x, a2.y, a3.x, a3.y);
    }
}

// =====================================================================
// Bin GEMM with split-K: C[o 128][i 128] += sum_p A[p][o] * B[p][i]
// A = y2[bk][p][mt*128 + o] (ld 256), B = y1[bk][p][i] (ld 128).
// grid: x = split (16), y = mtile (2), z = bk (36). 256 threads, 8x8 microtile.
// =====================================================================
__global__ void __launch_bounds__(256, 2)
gemm_part_kernel()
{
    __shared__ __align__(16) float As[16 * 128];
    __shared__ __align__(16) float Bs[16 * 128];

    const int s  = blockIdx.x;
    const int mt = blockIdx.y;
    const int bk = blockIdx.z;
    const int t  = threadIdx.x;
    const int ogrp = t >> 4;          // 0..15
    const int igrp = t & 15;          // 0..15

    const float* __restrict__ A = g_y2 + (size_t)bk * LPOS * COUTB + mt * 128;
    const float* __restrict__ B = g_y1 + (size_t)bk * LPOS * CIN;

    unsigned long long acc[8][4];
#pragma unroll
    for (int oo = 0; oo < 8; oo++)
#pragma unroll
        for (int q = 0; q < 4; q++) acc[oo][q] = 0ull;

    const int pBase = s * (LPOS / 16);   // 1024 positions per split
    for (int pc = 0; pc < LPOS / 16; pc += 16) {
        const int p0 = pBase + pc;
#pragma unroll
        for (int u = 0; u < 2; u++) {
            int f    = t + u * 256;
            int row  = f >> 5;
            int col4 = (f & 31) << 2;
            *(float4*)&As[row * 128 + col4] =
                *(const float4*)&A[(size_t)(p0 + row) * COUTB + col4];
            *(float4*)&Bs[row * 128 + col4] =
                *(const float4*)&B[(size_t)(p0 + row) * CIN + col4];
        }
        __syncthreads();
#pragma unroll
        for (int k = 0; k < 16; k++) {
            float4 a0 = *(const float4*)&As[k * 128 + ogrp * 8];
            float4 a1 = *(const float4*)&As[k * 128 + ogrp * 8 + 4];
            const unsigned long long* bp =
                (const unsigned long long*)&Bs[k * 128 + igrp * 8];
            unsigned long long b0 = bp[0], b1 = bp[1], b2 = bp[2], b3 = bp[3];
            float av[8] = {a0.x, a0.y, a0.z, a0.w, a1.x, a1.y, a1.z, a1.w};
#pragma unroll
            for (int oo = 0; oo < 8; oo++) {
                unsigned long long ap = pack2(av[oo], av[oo]);
                acc[oo][0] = fma2(b0, ap, acc[oo][0]);
                acc[oo][1] = fma2(b1, ap, acc[oo][1]);
                acc[oo][2] = fma2(b2, ap, acc[oo][2]);
                acc[oo][3] = fma2(b3, ap, acc[oo][3]);
            }
        }
        __syncthreads();
    }

    float* dst = g_part + (size_t)((bk * 2 + mt) * 16 + s) * 16384;
#pragma unroll
    for (int oo = 0; oo < 8; oo++) {
        float2 q0 = unpack2(acc[oo][0]);
        float2 q1 = unpack2(acc[oo][1]);
        float2 q2 = unpack2(acc[oo][2]);
        float2 q3 = unpack2(acc[oo][3]);
        float* d = dst + (size_t)(ogrp * 8 + oo) * 128 + igrp * 8;
        *(float4*)d       = make_float4(q0.x, q0.y, q1.x, q1.y);
        *(float4*)(d + 4) = make_float4(q2.x, q2.y, q3.x, q3.y);
    }
}

// =====================================================================
// Split-K reduce + scale + softmax over (i*9 + k), one block per (b,o).
// =====================================================================
__global__ void __launch_bounds__(128)
softmax_kernel(float* __restrict__ out)
{
    const int bo = blockIdx.x;         // b*256 + o
    const int b  = bo >> 8;
    const int o  = bo & 255;
    const int mt = o >> 7;
    const int ol = o & 127;
    const int i  = threadIdx.x;        // 0..127

    const float SCALE = 0.029462782549439476f;   // 1/sqrt(1152)

    float lg[9];
#pragma unroll
    for (int k = 0; k < 9; k++) {
        const float* p = g_part
            + (size_t)(((b * 9 + k) * 2 + mt) * 16) * 16384
            + (size_t)ol * 128 + i;
        float sum = 0.f;
#pragma unroll
        for (int s = 0; s < 16; s++) sum += p[(size_t)s * 16384];
        lg[k] = sum * SCALE;
    }

    // block max
    float m = lg[0];
#pragma unroll
    for (int k = 1; k < 9; k++) m = fmaxf(m, lg[k]);
#pragma unroll
    for (int off = 16; off; off >>= 1)
        m = fmaxf(m, __shfl_xor_sync(0xffffffffu, m, off));
    __shared__ float smax[4];
    if ((i & 31) == 0) smax[i >> 5] = m;
    __syncthreads();
    m = fmaxf(fmaxf(smax[0], smax[1]), fmaxf(smax[2], smax[3]));

    float e[9];
    float ls = 0.f;
#pragma unroll
    for (int k = 0; k < 9; k++) { e[k] = expf(lg[k] - m); ls += e[k]; }
#pragma unroll
    for (int off = 16; off; off >>= 1)
        ls += __shfl_xor_sync(0xffffffffu, ls, off);
    __shared__ float ssum[4];
    if ((i & 31) == 0) ssum[i >> 5] = ls;
    __syncthreads();
    ls = (ssum[0] + ssum[1]) + (ssum[2] + ssum[3]);
    float inv = 1.f / ls;

    float* dst = out + ((size_t)bo * 128 + i) * 9;
#pragma unroll
    for (int k = 0; k < 9; k++) dst[k] = e[k] * inv;
}

// =====================================================================
extern "C" void kernel_launch(void* const* d_in, const int* in_sizes, int n_in,
                              void* d_out, int out_size)
{
    const float* x  = (const float*)d_in[0];
    const float* w1 = (const float*)d_in[1];
    const float* w2 = (const float*)d_in[2];
    float* out = (float*)d_out;

    dim3 cgrid1(HW / 32, HW / 8, NB * (CIN / 32));
    conv_bin_kernel<CIN><<<cgrid1, 256>>>(x, w1);

    dim3 cgrid2(HW / 32, HW / 8, NB * (COUTB / 32));
    conv_bin_kernel<COUTB><<<cgrid2, 256>>>(x, w2);

    dim3 ggrid(16, 2, 36);
    gemm_part_kernel<<<ggrid, 256>>>();

    softmax_kernel<<<NB * COUTB, 128>>>(out);
}

// round 8
// speedup vs baseline: 1.0022x; 1.0022x over previous
#include <cuda_runtime.h>
#include <math.h>
#include <stdint.h>

#define CIN   128
#define COUTB 256
#define HW    384
#define LPOS  16384            // (384/3)^2 patches
#define NB    4

// ---------------- scratch (static __device__; no allocations allowed) ----------------
// y layout: [b*9+k][p][c]  (c innermost -> GEMM reads rows of channels, coalesced)
__device__ float g_y1[(size_t)NB * 9 * LPOS * CIN];     // 302 MB
__device__ float g_y2[(size_t)NB * 9 * LPOS * COUTB];   // 604 MB
// split-K partials: [(bk*2+mt)*16+s][o 128][i 128]
__device__ float g_part[(size_t)36 * 2 * 16 * 128 * 128];  // 75.5 MB

// ---------------- f32x2 helpers ----------------
__device__ __forceinline__ unsigned long long pack2(float x, float y) {
    unsigned long long r;
    asm("mov.b64 %0, {%1,%2};" : "=l"(r) : "f"(x), "f"(y));
    return r;
}
__device__ __forceinline__ unsigned long long fma2(unsigned long long a,
                                                   unsigned long long b,
                                                   unsigned long long c) {
    unsigned long long d;
    asm("fma.rn.f32x2 %0, %1, %2, %3;" : "=l"(d) : "l"(a), "l"(b), "l"(c));
    return d;
}
__device__ __forceinline__ float2 unpack2(unsigned long long v) {
    float2 f;
    asm("mov.b64 {%0,%1}, %2;" : "=f"(f.x), "=f"(f.y) : "l"(v));
    return f;
}

// =====================================================================
// Conv 3x3 (pad 1) + unfold-bin scatter.
// Tile: 32 couts x (8 rows x 32 cols). 256 threads.
// thread: cogrp = t/64 (8 couts as 4 f32x2 pairs), 4 adjacent pixels.
// =====================================================================
template <int COUT>
__global__ void __launch_bounds__(256, 2)
conv_bin_kernel(const float* __restrict__ x, const float* __restrict__ w)
{
    __shared__ __align__(16) float xs[8 * 10 * 36];   // [ci 8][row 10][col 34 pad 36]
    __shared__ __align__(16) float ws[8 * 9 * 32];    // [ci 8][tap 9][co 32]

    float* __restrict__ ys = (COUT == CIN) ? g_y1 : g_y2;

    const int colBase = blockIdx.x * 32;
    const int rowBase = blockIdx.y * 8;
    const int nct     = COUT / 32;
    const int ct      = blockIdx.z % nct;
    const int b       = blockIdx.z / nct;
    const int co0     = ct * 32;

    const int t     = threadIdx.x;
    const int cogrp = t >> 6;           // 0..3 -> co sub-base cogrp*8
    const int pxg   = t & 63;           // 0..63
    const int r     = pxg >> 3;         // 0..7 local row
    const int c0    = (pxg & 7) * 4;    // local col base (4 px per thread)

    const float* __restrict__ xb = x + (size_t)b * CIN * HW * HW;

    unsigned long long acc[4][4];
#pragma unroll
    for (int j = 0; j < 4; j++)
#pragma unroll
        for (int q = 0; q < 4; q++) acc[j][q] = 0ull;

    for (int ci0 = 0; ci0 < CIN; ci0 += 8) {
        // ---- stage x chunk: 8 ch x 10 x 34 (halo, zero-padded) ----
        for (int e = t; e < 8 * 10 * 34; e += 256) {
            int cc  = e / 340;
            int rem = e - cc * 340;
            int rr  = rem / 34;
            int cl  = rem - rr * 34;
            int gr  = rowBase - 1 + rr;
            int gc  = colBase - 1 + cl;
            float v = 0.f;
            if ((unsigned)gr < HW && (unsigned)gc < HW)
                v = xb[((size_t)(ci0 + cc) * HW + gr) * HW + gc];
            xs[cc * 360 + rr * 36 + cl] = v;
        }
        // ---- stage w chunk: ws[cc][tap][co] ----
        for (int e = t; e < 8 * 9 * 32; e += 256) {
            int cc  = e / 288;
            int rem = e - cc * 288;
            int t9  = rem >> 5;
            int co  = rem & 31;
            ws[cc * 288 + t9 * 32 + co] =
                w[((size_t)(co0 + co) * CIN + (ci0 + cc)) * 9 + t9];
        }
        __syncthreads();

#pragma unroll 2
        for (int cc = 0; cc < 8; cc++) {
            const float* xr = &xs[cc * 360 + r * 36 + c0];
            float xv[3][6];
#pragma unroll
            for (int kh = 0; kh < 3; kh++) {
                float4 v4 = *(const float4*)(xr + kh * 36);
                float2 v2 = *(const float2*)(xr + kh * 36 + 4);
                xv[kh][0] = v4.x; xv[kh][1] = v4.y; xv[kh][2] = v4.z;
                xv[kh][3] = v4.w; xv[kh][4] = v2.x; xv[kh][5] = v2.y;
            }
            // warp-uniform weight pairs (broadcast LDS.64)
            const unsigned long long* wr =
                (const unsigned long long*)&ws[cc * 288 + cogrp * 8];
#pragma unroll
            for (int kh = 0; kh < 3; kh++) {
#pragma unroll
                for (int kw = 0; kw < 3; kw++) {
                    const int t9 = kh * 3 + kw;
                    unsigned long long w0 = wr[t9 * 16 + 0];
                    unsigned long long w1 = wr[t9 * 16 + 1];
                    unsigned long long w2 = wr[t9 * 16 + 2];
                    unsigned long long w3 = wr[t9 * 16 + 3];
#pragma unroll
                    for (int j = 0; j < 4; j++) {
                        unsigned long long xb2 = pack2(xv[kh][kw + j], xv[kh][kw + j]);
                        acc[j][0] = fma2(w0, xb2, acc[j][0]);
                        acc[j][1] = fma2(w1, xb2, acc[j][1]);
                        acc[j][2] = fma2(w2, xb2, acc[j][2]);
                        acc[j][3] = fma2(w3, xb2, acc[j][3]);
                    }
                }
            }
        }
        __syncthreads();
    }

    // ---- epilogue: scatter into bin layout y[(b*9+k)][p][c] ----
    const int h = rowBase + r;
#pragma unroll
    for (int j = 0; j < 4; j++) {
        int wc = colBase + c0 + j;
        int k  = (h % 3) * 3 + (wc % 3);
        int p  = (h / 3) * 128 + (wc / 3);
        float* dst = ys + (((size_t)(b * 9 + k) * LPOS + p) * COUT + co0 + cogrp * 8);
        float2 a0 = unpack2(acc[j][0]);
        float2 a1 = unpack2(acc[j][1]);
        float2 a2 = unpack2(acc[j][2]);
        float2 a3 = unpack2(acc[j][3]);
        *(float4*)dst       = make_float4(a0.x, a0.y, a1.x, a1.y);
        *(float4*)(dst + 4) = make_float4(a2.x, a2.y, a3.x, a3.y);
    }
}

// =====================================================================
// Bin GEMM with split-K: C[o 128][i 128] += sum_p A[p][o] * B[p][i]
// A = y2[bk][p][mt*128 + o] (ld 256), B = y1[bk][p][i] (ld 128).
// grid: x = split (16), y = mtile (2), z = bk (36). 256 threads, 8x8 microtile.
// =====================================================================
__global__ void __launch_bounds__(256, 2)
gemm_part_kernel()
{
    __shared__ __align__(16) float As[16 * 128];
    __shared__ __align__(16) float Bs[16 * 128];

    const int s  = blockIdx.x;
    const int mt = blockIdx.y;
    const int bk = blockIdx.z;
    const int t  = threadIdx.x;
    const int ogrp = t >> 4;          // 0..15
    const int igrp = t & 15;          // 0..15

    const float* __restrict__ A = g_y2 + (size_t)bk * LPOS * COUTB + mt * 128;
    const float* __restrict__ B = g_y1 + (size_t)bk * LPOS * CIN;

    unsigned long long acc[8][4];
#pragma unroll
    for (int oo = 0; oo < 8; oo++)
#pragma unroll
        for (int q = 0; q < 4; q++) acc[oo][q] = 0ull;

    const int pBase = s * (LPOS / 16);   // 1024 positions per split
    for (int pc = 0; pc < LPOS / 16; pc += 16) {
        const int p0 = pBase + pc;
#pragma unroll
        for (int u = 0; u < 2; u++) {
            int f    = t + u * 256;
            int row  = f >> 5;
            int col4 = (f & 31) << 2;
            *(float4*)&As[row * 128 + col4] =
                *(const float4*)&A[(size_t)(p0 + row) * COUTB + col4];
            *(float4*)&Bs[row * 128 + col4] =
                *(const float4*)&B[(size_t)(p0 + row) * CIN + col4];
        }
        __syncthreads();
#pragma unroll
        for (int k = 0; k < 16; k++) {
            float4 a0 = *(const float4*)&As[k * 128 + ogrp * 8];
            float4 a1 = *(const float4*)&As[k * 128 + ogrp * 8 + 4];
            const unsigned long long* bp =
                (const unsigned long long*)&Bs[k * 128 + igrp * 8];
            unsigned long long b0 = bp[0], b1 = bp[1], b2 = bp[2], b3 = bp[3];
            float av[8] = {a0.x, a0.y, a0.z, a0.w, a1.x, a1.y, a1.z, a1.w};
#pragma unroll
            for (int oo = 0; oo < 8; oo++) {
                unsigned long long ap = pack2(av[oo], av[oo]);
                acc[oo][0] = fma2(b0, ap, acc[oo][0]);
                acc[oo][1] = fma2(b1, ap, acc[oo][1]);
                acc[oo][2] = fma2(b2, ap, acc[oo][2]);
                acc[oo][3] = fma2(b3, ap, acc[oo][3]);
            }
        }
        __syncthreads();
    }

    float* dst = g_part + (size_t)((bk * 2 + mt) * 16 + s) * 16384;
#pragma unroll
    for (int oo = 0; oo < 8; oo++) {
        float2 q0 = unpack2(acc[oo][0]);
        float2 q1 = unpack2(acc[oo][1]);
        float2 q2 = unpack2(acc[oo][2]);
        float2 q3 = unpack2(acc[oo][3]);
        float* d = dst + (size_t)(ogrp * 8 + oo) * 128 + igrp * 8;
        *(float4*)d       = make_float4(q0.x, q0.y, q1.x, q1.y);
        *(float4*)(d + 4) = make_float4(q2.x, q2.y, q3.x, q3.y);
    }
}

// =====================================================================
// Split-K reduce + scale + softmax over (i*9 + k), one block per (b,o).
// =====================================================================
__global__ void __launch_bounds__(128)
softmax_kernel(float* __restrict__ out)
{
    const int bo = blockIdx.x;         // b*256 + o
    const int b  = bo >> 8;
    const int o  = bo & 255;
    const int mt = o >> 7;
    const int ol = o & 127;
    const int i  = threadIdx.x;        // 0..127

    const float SCALE = 0.029462782549439476f;   // 1/sqrt(1152)

    float lg[9];
#pragma unroll
    for (int k = 0; k < 9; k++) {
        const float* p = g_part
            + (size_t)(((b * 9 + k) * 2 + mt) * 16) * 16384
            + (size_t)ol * 128 + i;
        float sum = 0.f;
#pragma unroll
        for (int s = 0; s < 16; s++) sum += p[(size_t)s * 16384];
        lg[k] = sum * SCALE;
    }

    // block max
    float m = lg[0];
#pragma unroll
    for (int k = 1; k < 9; k++) m = fmaxf(m, lg[k]);
#pragma unroll
    for (int off = 16; off; off >>= 1)
        m = fmaxf(m, __shfl_xor_sync(0xffffffffu, m, off));
    __shared__ float smax[4];
    if ((i & 31) == 0) smax[i >> 5] = m;
    __syncthreads();
    m = fmaxf(fmaxf(smax[0], smax[1]), fmaxf(smax[2], smax[3]));

    float e[9];
    float ls = 0.f;
#pragma unroll
    for (int k = 0; k < 9; k++) { e[k] = expf(lg[k] - m); ls += e[k]; }
#pragma unroll
    for (int off = 16; off; off >>= 1)
        ls += __shfl_xor_sync(0xffffffffu, ls, off);
    __shared__ float ssum[4];
    if ((i & 31) == 0) ssum[i >> 5] = ls;
    __syncthreads();
    ls = (ssum[0] + ssum[1]) + (ssum[2] + ssum[3]);
    float inv = 1.f / ls;

    float* dst = out + ((size_t)bo * 128 + i) * 9;
#pragma unroll
    for (int k = 0; k < 9; k++) dst[k] = e[k] * inv;
}

// =====================================================================
extern "C" void kernel_launch(void* const* d_in, const int* in_sizes, int n_in,
                              void* d_out, int out_size)
{
    const float* x  = (const float*)d_in[0];
    const float* w1 = (const float*)d_in[1];
    const float* w2 = (const float*)d_in[2];
    float* out = (float*)d_out;

    dim3 cgrid1(HW / 32, HW / 8, NB * (CIN / 32));
    conv_bin_kernel<CIN><<<cgrid1, 256>>>(x, w1);

    dim3 cgrid2(HW / 32, HW / 8, NB * (COUTB / 32));
    conv_bin_kernel<COUTB><<<cgrid2, 256>>>(x, w2);

    dim3 ggrid(16, 2, 36);
    gemm_part_kernel<<<ggrid, 256>>>();

    softmax_kernel<<<NB * COUTB, 128>>>(out);
}

// round 10
// speedup vs baseline: 1.4295x; 1.4264x over previous
#include <cuda_runtime.h>
#include <math.h>
#include <stdint.h>

#define CIN   128
#define COUTB 256
#define HW    384
#define LPOS  16384
#define NB    4
#define PADW  386
#define PPOS  (PADW*PADW)
#define MTOT  384
#define KTOT  1152

// ---------------- static device scratch ----------------
__device__ __align__(16) float g_y1[(size_t)NB * 9 * LPOS * CIN];
__device__ __align__(16) float g_y2[(size_t)NB * 9 * LPOS * COUTB];
__device__ __align__(16) float g_part[(size_t)36 * 2 * 16 * 128 * 128];
__device__ __align__(16) float g_xph[(size_t)NB * PPOS * CIN];
__device__ __align__(16) float g_xpl[(size_t)NB * PPOS * CIN];
__device__ __align__(16) float g_wh[(size_t)MTOT * KTOT];
__device__ __align__(16) float g_wl[(size_t)MTOT * KTOT];

// ---------------- helpers ----------------
__device__ __forceinline__ unsigned long long pack2(float x, float y) {
    unsigned long long r; asm("mov.b64 %0, {%1,%2};" : "=l"(r) : "f"(x), "f"(y)); return r;
}
__device__ __forceinline__ unsigned long long fma2(unsigned long long a, unsigned long long b, unsigned long long c) {
    unsigned long long d; asm("fma.rn.f32x2 %0, %1, %2, %3;" : "=l"(d) : "l"(a), "l"(b), "l"(c)); return d;
}
__device__ __forceinline__ float2 unpack2(unsigned long long v) {
    float2 f; asm("mov.b64 {%0,%1}, %2;" : "=f"(f.x), "=f"(f.y) : "l"(v)); return f;
}
__device__ __forceinline__ float tf32r(float x) {
    uint32_t u; asm("cvt.rna.tf32.f32 %0, %1;" : "=r"(u) : "f"(x)); return __uint_as_float(u);
}
__device__ __forceinline__ uint32_t s2u(const void* p) {
    uint32_t a; asm("{ .reg .u64 t; cvta.to.shared.u64 t, %1; cvt.u32.u64 %0, t; }" : "=r"(a) : "l"(p)); return a;
}
__device__ __forceinline__ void cpa16(uint32_t dst, const void* src) {
    asm volatile("cp.async.cg.shared.global [%0], [%1], 16;" :: "r"(dst), "l"(src));
}
__device__ __forceinline__ void mma168(float* d, const uint32_t* a, const uint32_t* b) {
    asm volatile("mma.sync.aligned.m16n8k8.row.col.f32.tf32.tf32.f32 "
        "{%0,%1,%2,%3}, {%4,%5,%6,%7}, {%8,%9}, {%0,%1,%2,%3};"
        : "+f"(d[0]), "+f"(d[1]), "+f"(d[2]), "+f"(d[3])
        : "r"(a[0]), "r"(a[1]), "r"(a[2]), "r"(a[3]), "r"(b[0]), "r"(b[1]));
}

// =====================================================================
// prep: padded transposed input [b][pos(h'*386+w')][ci], tf32 hi/lo split
// =====================================================================
__global__ void prep_x_kernel(const float* __restrict__ x)
{
    __shared__ float tile[32][33];
    const int wx = blockIdx.x, hp = blockIdx.y;
    const int ct = blockIdx.z & 3, b = blockIdx.z >> 2;
    const int tx = threadIdx.x, ty = threadIdx.y;
    const int h = hp - 1;
#pragma unroll
    for (int i = 0; i < 4; i++) {
        int cil = ty + i * 8;
        int wp  = wx * 32 + tx;
        int w   = wp - 1;
        float v = 0.f;
        if ((unsigned)h < HW && (unsigned)w < HW)
            v = x[(((size_t)b * CIN + ct * 32 + cil) * HW + h) * HW + w];
        tile[cil][tx] = v;
    }
    __syncthreads();
#pragma unroll
    for (int i = 0; i < 4; i++) {
        int wl = ty + i * 8;
        int wp = wx * 32 + wl;
        if (wp < PADW) {
            float v  = tile[tx][wl];
            float hi = tf32r(v);
            float lo = tf32r(v - hi);
            size_t idx = ((size_t)b * PPOS + (size_t)hp * PADW + wp) * CIN + ct * 32 + tx;
            g_xph[idx] = hi;
            g_xpl[idx] = lo;
        }
    }
}

__global__ void prep_w_kernel(const float* __restrict__ w1, const float* __restrict__ w2)
{
    int idx = blockIdx.x * 256 + threadIdx.x;
    if (idx >= MTOT * KTOT) return;
    int co = idx / KTOT, kk = idx - co * KTOT;
    int tp = kk >> 7, ci = kk & 127;
    float v = (co < CIN) ? w1[((size_t)co * CIN + ci) * 9 + tp]
                         : w2[((size_t)(co - CIN) * CIN + ci) * 9 + tp];
    float hi = tf32r(v);
    g_wh[idx] = hi;
    g_wl[idx] = tf32r(v - hi);
}

// =====================================================================
// conv as implicit GEMM on mma.sync tf32 (3xTF32 emulation).
// Block: D[128 pos][192 co], K=1152 in 72 chunks of 16, double-buffered.
// 8 warps = 2(M) x 4(N); warp tile 64x48; m16n8k8 frags.
// smem per stage (floats): Ah 128*20, Al 128*20, Bh 192*20, Bl 192*20
// =====================================================================
#define STG_F   12800                     // floats per stage
#define OFF_AL  2560
#define OFF_BH  5120
#define OFF_BL  8960
#define SMEM_BYTES (2 * STG_F * 4)        // 102400

__global__ void __launch_bounds__(256, 1) conv_mma_kernel()
{
    extern __shared__ float sm[];
    const int t  = threadIdx.x;
    const int l  = t & 31, wrp = t >> 5;
    const int mw = wrp & 1, nw = wrp >> 1;
    const int q  = l >> 2, tq = l & 3;

    const int w0    = blockIdx.x * 128;
    const int nbase = blockIdx.y * 192;
    const int h     = blockIdx.z % HW;
    const int b     = blockIdx.z / HW;

    const float* __restrict__ xph = g_xph + (size_t)b * PPOS * CIN;
    const float* __restrict__ xpl = g_xpl + (size_t)b * PPOS * CIN;
    const uint32_t smb = s2u(sm);

    float acc[4][6][4];
#pragma unroll
    for (int i = 0; i < 4; i++)
#pragma unroll
        for (int j = 0; j < 6; j++)
#pragma unroll
            for (int r = 0; r < 4; r++) acc[i][j][r] = 0.f;

    auto load_chunk = [&](int c, int buf) {
        const int tap = c >> 3, ci0 = (c & 7) * 16;
        const int kh = tap / 3, kw = tap - kh * 3;
        const size_t ab = ((size_t)(h + kh) * PADW + (w0 + kw)) * CIN + ci0;
        const uint32_t base = smb + buf * (STG_F * 4);
#pragma unroll
        for (int i = 0; i < 2; i++) {
            int e = t + i * 256, p = e >> 2, k4 = e & 3;
            uint32_t o = (p * 20 + k4 * 4) * 4;
            const float* src = xph + ab + (size_t)p * CIN + k4 * 4;
            cpa16(base + o, src);
            cpa16(base + OFF_AL * 4 + o, src + (g_xpl - g_xph));
        }
        const size_t wb = (size_t)tap * 128 + ci0;
#pragma unroll
        for (int i = 0; i < 3; i++) {
            int e = t + i * 256, n = e >> 2, k4 = e & 3;
            uint32_t o = (n * 20 + k4 * 4) * 4;
            size_t so = (size_t)(nbase + n) * KTOT + wb + k4 * 4;
            cpa16(base + OFF_BH * 4 + o, g_wh + so);
            cpa16(base + OFF_BL * 4 + o, g_wl + so);
        }
        asm volatile("cp.async.commit_group;" ::: "memory");
    };

    load_chunk(0, 0);

    for (int c = 0; c < 72; c++) {
        const int buf = c & 1;
        if (c < 71) {
            load_chunk(c + 1, buf ^ 1);
            asm volatile("cp.async.wait_group 1;" ::: "memory");
        } else {
            asm volatile("cp.async.wait_group 0;" ::: "memory");
        }
        __syncthreads();

        const float* Ah = sm + buf * STG_F;
        const float* Al = Ah + OFF_AL;
        const float* Bh = Ah + OFF_BH;
        const float* Bl = Ah + OFF_BL;

#pragma unroll
        for (int ks = 0; ks < 2; ks++) {
            uint32_t ah[4][4], al[4][4];
#pragma unroll
            for (int i = 0; i < 4; i++) {
                int base = (mw * 64 + i * 16 + q) * 20 + ks * 8 + tq;
                ah[i][0] = __float_as_uint(Ah[base]);
                ah[i][1] = __float_as_uint(Ah[base + 160]);
                ah[i][2] = __float_as_uint(Ah[base + 4]);
                ah[i][3] = __float_as_uint(Ah[base + 164]);
                al[i][0] = __float_as_uint(Al[base]);
                al[i][1] = __float_as_uint(Al[base + 160]);
                al[i][2] = __float_as_uint(Al[base + 4]);
                al[i][3] = __float_as_uint(Al[base + 164]);
            }
#pragma unroll
            for (int j = 0; j < 6; j++) {
                int nb_ = (nw * 48 + j * 8 + q) * 20 + ks * 8 + tq;
                uint32_t bh[2] = { __float_as_uint(Bh[nb_]), __float_as_uint(Bh[nb_ + 4]) };
                uint32_t bl[2] = { __float_as_uint(Bl[nb_]), __float_as_uint(Bl[nb_ + 4]) };
#pragma unroll
                for (int i = 0; i < 4; i++) {
                    mma168(acc[i][j], ah[i], bh);   // hi*hi
                    mma168(acc[i][j], al[i], bh);   // lo*hi
                    mma168(acc[i][j], ah[i], bl);   // hi*lo
                }
            }
        }
        __syncthreads();
    }

    // ---- epilogue: scatter accumulators into bin layout ----
#pragma unroll
    for (int i = 0; i < 4; i++) {
#pragma unroll
        for (int hf = 0; hf < 2; hf++) {
            int w = w0 + mw * 64 + i * 16 + q + hf * 8;
            int k = (h % 3) * 3 + (w % 3);
            size_t p   = (size_t)(h / 3) * 128 + (w / 3);
            size_t row = (size_t)(b * 9 + k) * LPOS + p;
            float* y1r = g_y1 + row * CIN;
            float* y2r = g_y2 + row * COUTB;
#pragma unroll
            for (int j = 0; j < 6; j++) {
                int co = nbase + nw * 48 + j * 8 + tq * 2;
                float2 v = make_float2(acc[i][j][hf * 2], acc[i][j][hf * 2 + 1]);
                if (co < CIN) *(float2*)(y1r + co) = v;
                else          *(float2*)(y2r + co - CIN) = v;
            }
        }
    }
}

// =====================================================================
// stage 2: bin GEMM with split-K (proven)
// =====================================================================
__global__ void __launch_bounds__(256, 2) gemm_part_kernel()
{
    __shared__ __align__(16) float As[16 * 128];
    __shared__ __align__(16) float Bs[16 * 128];
    const int s = blockIdx.x, mt = blockIdx.y, bk = blockIdx.z;
    const int t = threadIdx.x, ogrp = t >> 4, igrp = t & 15;
    const float* __restrict__ A = g_y2 + (size_t)bk * LPOS * COUTB + mt * 128;
    const float* __restrict__ B = g_y1 + (size_t)bk * LPOS * CIN;
    unsigned long long acc[8][4];
#pragma unroll
    for (int oo = 0; oo < 8; oo++)
#pragma unroll
        for (int qq = 0; qq < 4; qq++) acc[oo][qq] = 0ull;
    const int pBase = s * (LPOS / 16);
    for (int pc = 0; pc < LPOS / 16; pc += 16) {
        const int p0 = pBase + pc;
#pragma unroll
        for (int u = 0; u < 2; u++) {
            int f = t + u * 256, row = f >> 5, col4 = (f & 31) << 2;
            *(float4*)&As[row * 128 + col4] = *(const float4*)&A[(size_t)(p0 + row) * COUTB + col4];
            *(float4*)&Bs[row * 128 + col4] = *(const float4*)&B[(size_t)(p0 + row) * CIN + col4];
        }
        __syncthreads();
#pragma unroll
        for (int k = 0; k < 16; k++) {
            float4 a0 = *(const float4*)&As[k * 128 + ogrp * 8];
            float4 a1 = *(const float4*)&As[k * 128 + ogrp * 8 + 4];
            const unsigned long long* bp = (const unsigned long long*)&Bs[k * 128 + igrp * 8];
            unsigned long long b0 = bp[0], b1 = bp[1], b2 = bp[2], b3 = bp[3];
            float av[8] = {a0.x, a0.y, a0.z, a0.w, a1.x, a1.y, a1.z, a1.w};
#pragma unroll
            for (int oo = 0; oo < 8; oo++) {
                unsigned long long ap = pack2(av[oo], av[oo]);
                acc[oo][0] = fma2(b0, ap, acc[oo][0]);
                acc[oo][1] = fma2(b1, ap, acc[oo][1]);
                acc[oo][2] = fma2(b2, ap, acc[oo][2]);
                acc[oo][3] = fma2(b3, ap, acc[oo][3]);
            }
        }
        __syncthreads();
    }
    float* dst = g_part + (size_t)((bk * 2 + mt) * 16 + s) * 16384;
#pragma unroll
    for (int oo = 0; oo < 8; oo++) {
        float2 q0 = unpack2(acc[oo][0]), q1 = unpack2(acc[oo][1]);
        float2 q2 = unpack2(acc[oo][2]), q3 = unpack2(acc[oo][3]);
        float* d = dst + (size_t)(ogrp * 8 + oo) * 128 + igrp * 8;
        *(float4*)d       = make_float4(q0.x, q0.y, q1.x, q1.y);
        *(float4*)(d + 4) = make_float4(q2.x, q2.y, q3.x, q3.y);
    }
}

// =====================================================================
// split-K reduce + softmax (proven)
// =====================================================================
__global__ void __launch_bounds__(128) softmax_kernel(float* __restrict__ out)
{
    const int bo = blockIdx.x, b = bo >> 8, o = bo & 255;
    const int mt = o >> 7, ol = o & 127, i = threadIdx.x;
    const float SCALE = 0.029462782549439476f;
    float lg[9];
#pragma unroll
    for (int k = 0; k < 9; k++) {
        const float* p = g_part + (size_t)(((b * 9 + k) * 2 + mt) * 16) * 16384 + (size_t)ol * 128 + i;
        float sum = 0.f;
#pragma unroll
        for (int s = 0; s < 16; s++) sum += p[(size_t)s * 16384];
        lg[k] = sum * SCALE;
    }
    float m = lg[0];
#pragma unroll
    for (int k = 1; k < 9; k++) m = fmaxf(m, lg[k]);
#pragma unroll
    for (int off = 16; off; off >>= 1) m = fmaxf(m, __shfl_xor_sync(0xffffffffu, m, off));
    __shared__ float smax[4];
    if ((i & 31) == 0) smax[i >> 5] = m;
    __syncthreads();
    m = fmaxf(fmaxf(smax[0], smax[1]), fmaxf(smax[2], smax[3]));
    float e[9], ls = 0.f;
#pragma unroll
    for (int k = 0; k < 9; k++) { e[k] = expf(lg[k] - m); ls += e[k]; }
#pragma unroll
    for (int off = 16; off; off >>= 1) ls += __shfl_xor_sync(0xffffffffu, ls, off);
    __shared__ float ssum[4];
    if ((i & 31) == 0) ssum[i >> 5] = ls;
    __syncthreads();
    ls = (ssum[0] + ssum[1]) + (ssum[2] + ssum[3]);
    float inv = 1.f / ls;
    float* dst = out + ((size_t)bo * 128 + i) * 9;
#pragma unroll
    for (int k = 0; k < 9; k++) dst[k] = e[k] * inv;
}

// =====================================================================
extern "C" void kernel_launch(void* const* d_in, const int* in_sizes, int n_in,
                              void* d_out, int out_size)
{
    const float* x  = (const float*)d_in[0];
    const float* w1 = (const float*)d_in[1];
    const float* w2 = (const float*)d_in[2];
    float* out = (float*)d_out;

    cudaFuncSetAttribute(conv_mma_kernel, cudaFuncAttributeMaxDynamicSharedMemorySize, SMEM_BYTES);

    prep_x_kernel<<<dim3((PADW + 31) / 32, PADW, NB * 4), dim3(32, 8)>>>(x);
    prep_w_kernel<<<(MTOT * KTOT + 255) / 256, 256>>>(w1, w2);
    conv_mma_kernel<<<dim3(3, 2, HW * NB), 256, SMEM_BYTES>>>();
    gemm_part_kernel<<<dim3(16, 2, 36), 256>>>();
    softmax_kernel<<<NB * COUTB, 128>>>(out);
}

// round 11
// speedup vs baseline: 2.3634x; 1.6532x over previous
#include <cuda_runtime.h>
#include <cuda_fp16.h>
#include <math.h>
#include <stdint.h>

#define CIN   128
#define COUTB 256
#define HW    384
#define LPOS  16384
#define NB    4
#define PADW  386
#define PPOS  (PADW*PADW)
#define MTOT  384
#define KTOT  1152

// ---------------- static device scratch ----------------
__device__ __align__(16) float  g_y1[(size_t)NB * 9 * LPOS * CIN];
__device__ __align__(16) float  g_y2[(size_t)NB * 9 * LPOS * COUTB];
__device__ __align__(16) float  g_part[(size_t)36 * 2 * 16 * 128 * 128];
__device__ __align__(16) __half g_xhh[(size_t)NB * PPOS * CIN];   // hi
__device__ __align__(16) __half g_xhl[(size_t)NB * PPOS * CIN];   // (x-hi)*2048
__device__ __align__(16) __half g_whh[(size_t)MTOT * KTOT];
__device__ __align__(16) __half g_whl[(size_t)MTOT * KTOT];

// ---------------- helpers ----------------
__device__ __forceinline__ unsigned long long pack2(float x, float y) {
    unsigned long long r; asm("mov.b64 %0, {%1,%2};" : "=l"(r) : "f"(x), "f"(y)); return r;
}
__device__ __forceinline__ unsigned long long fma2(unsigned long long a, unsigned long long b, unsigned long long c) {
    unsigned long long d; asm("fma.rn.f32x2 %0, %1, %2, %3;" : "=l"(d) : "l"(a), "l"(b), "l"(c)); return d;
}
__device__ __forceinline__ float2 unpack2(unsigned long long v) {
    float2 f; asm("mov.b64 {%0,%1}, %2;" : "=f"(f.x), "=f"(f.y) : "l"(v)); return f;
}
__device__ __forceinline__ uint32_t s2u(const void* p) {
    uint32_t a; asm("{ .reg .u64 t; cvta.to.shared.u64 t, %1; cvt.u32.u64 %0, t; }" : "=r"(a) : "l"(p)); return a;
}
__device__ __forceinline__ void cpa16(uint32_t dst, const void* src) {
    asm volatile("cp.async.cg.shared.global [%0], [%1], 16;" :: "r"(dst), "l"(src));
}
__device__ __forceinline__ void ldm4(uint32_t* r, uint32_t addr) {
    asm volatile("ldmatrix.sync.aligned.m8n8.x4.shared.b16 {%0,%1,%2,%3}, [%4];"
        : "=r"(r[0]), "=r"(r[1]), "=r"(r[2]), "=r"(r[3]) : "r"(addr));
}
__device__ __forceinline__ void ldm2(uint32_t* r, uint32_t addr) {
    asm volatile("ldmatrix.sync.aligned.m8n8.x2.shared.b16 {%0,%1}, [%2];"
        : "=r"(r[0]), "=r"(r[1]) : "r"(addr));
}
__device__ __forceinline__ void mma16816(float* d, const uint32_t* a, const uint32_t* b) {
    asm volatile("mma.sync.aligned.m16n8k16.row.col.f32.f16.f16.f32 "
        "{%0,%1,%2,%3}, {%4,%5,%6,%7}, {%8,%9}, {%0,%1,%2,%3};"
        : "+f"(d[0]), "+f"(d[1]), "+f"(d[2]), "+f"(d[3])
        : "r"(a[0]), "r"(a[1]), "r"(a[2]), "r"(a[3]), "r"(b[0]), "r"(b[1]));
}

// =====================================================================
// prep: padded transposed input [b][pos][ci], fp16 hi + scaled-lo split
// =====================================================================
__global__ void prep_x_kernel(const float* __restrict__ x)
{
    __shared__ float tile[32][33];
    const int wx = blockIdx.x, hp = blockIdx.y;
    const int ct = blockIdx.z & 3, b = blockIdx.z >> 2;
    const int tx = threadIdx.x, ty = threadIdx.y;
    const int h = hp - 1;
#pragma unroll
    for (int i = 0; i < 4; i++) {
        int cil = ty + i * 8;
        int wp  = wx * 32 + tx;
        int w   = wp - 1;
        float v = 0.f;
        if ((unsigned)h < HW && (unsigned)w < HW)
            v = x[(((size_t)b * CIN + ct * 32 + cil) * HW + h) * HW + w];
        tile[cil][tx] = v;
    }
    __syncthreads();
#pragma unroll
    for (int i = 0; i < 4; i++) {
        int wl = ty + i * 8;
        int wp = wx * 32 + wl;
        if (wp < PADW) {
            float v  = tile[tx][wl];
            __half hi = __float2half_rn(v);
            float  lo = (v - __half2float(hi)) * 2048.0f;
            size_t idx = ((size_t)b * PPOS + (size_t)hp * PADW + wp) * CIN + ct * 32 + tx;
            g_xhh[idx] = hi;
            g_xhl[idx] = __float2half_rn(lo);
        }
    }
}

__global__ void prep_w_kernel(const float* __restrict__ w1, const float* __restrict__ w2)
{
    int idx = blockIdx.x * 256 + threadIdx.x;
    if (idx >= MTOT * KTOT) return;
    int co = idx / KTOT, kk = idx - co * KTOT;
    int tp = kk >> 7, ci = kk & 127;
    float v = (co < CIN) ? w1[((size_t)co * CIN + ci) * 9 + tp]
                         : w2[((size_t)(co - CIN) * CIN + ci) * 9 + tp];
    __half hi = __float2half_rn(v);
    g_whh[idx] = hi;
    g_whl[idx] = __float2half_rn((v - __half2float(hi)) * 2048.0f);
}

// =====================================================================
// conv as implicit GEMM, split-FP16 mma.m16n8k16 (3 products, dual acc).
// Block: D[128 pos][128 co], K=1152 in 36 chunks of 32, double-buffered.
// 8 warps = 2(M) x 4(N); warp tile 64x32.
// smem rows: 40 halves (32 K + 8 pad) -> 80B stride, ldmatrix conflict-free.
// =====================================================================
#define STG_H   20480                 // halves per stage
#define OFF_AL  5120
#define OFF_BH  10240
#define OFF_BL  15360
#define SMEM_BYTES (2 * STG_H * 2)    // 81920

__global__ void __launch_bounds__(256, 1) conv_mma_kernel()
{
    extern __shared__ __half smh[];
    const int t  = threadIdx.x;
    const int l  = t & 31, wrp = t >> 5;
    const int mw = wrp & 1, nw = wrp >> 1;
    const int q  = l >> 2, tq = l & 3;

    const int w0    = blockIdx.x * 128;
    const int nbase = blockIdx.y * 128;
    const int h     = blockIdx.z % HW;
    const int b     = blockIdx.z / HW;

    const __half* __restrict__ xhh = g_xhh + (size_t)b * PPOS * CIN;
    const __half* __restrict__ xhl = g_xhl + (size_t)b * PPOS * CIN;
    const uint32_t smb = s2u(smh);

    float accA[4][4][4], accB[4][4][4];
#pragma unroll
    for (int i = 0; i < 4; i++)
#pragma unroll
        for (int j = 0; j < 4; j++)
#pragma unroll
            for (int r = 0; r < 4; r++) { accA[i][j][r] = 0.f; accB[i][j][r] = 0.f; }

    auto load_chunk = [&](int c, int buf) {
        const int tap = c >> 2, ci0 = (c & 3) * 32;
        const int kh = tap / 3, kw = tap - kh * 3;
        const size_t ab = ((size_t)(h + kh) * PADW + (w0 + kw)) * CIN + ci0;
        const uint32_t base = smb + buf * (STG_H * 2);
#pragma unroll
        for (int i = 0; i < 2; i++) {
            int e = t + i * 256, row = e >> 2, k8 = e & 3;
            uint32_t o = row * 80 + k8 * 16;
            const __half* src = xhh + ab + (size_t)row * CIN + k8 * 8;
            cpa16(base + o, src);
            cpa16(base + OFF_AL * 2 + o, src + (g_xhl - g_xhh));
        }
        const size_t wb = (size_t)tap * 128 + ci0;
#pragma unroll
        for (int i = 0; i < 2; i++) {
            int e = t + i * 256, row = e >> 2, k8 = e & 3;
            uint32_t o = row * 80 + k8 * 16;
            size_t so = (size_t)(nbase + row) * KTOT + wb + k8 * 8;
            cpa16(base + OFF_BH * 2 + o, g_whh + so);
            cpa16(base + OFF_BL * 2 + o, g_whl + so);
        }
        asm volatile("cp.async.commit_group;" ::: "memory");
    };

    load_chunk(0, 0);

    for (int c = 0; c < 36; c++) {
        const int buf = c & 1;
        if (c < 35) {
            load_chunk(c + 1, buf ^ 1);
            asm volatile("cp.async.wait_group 1;" ::: "memory");
        } else {
            asm volatile("cp.async.wait_group 0;" ::: "memory");
        }
        __syncthreads();

        const uint32_t base = smb + buf * (STG_H * 2);
        const int r8 = l & 7, ts = l >> 3;       // A tile select: bit0=+8 rows, bit1=+8 k
        const int rb = l & 7, tb = (l >> 3) & 1; // B tile select: +8 k

#pragma unroll
        for (int ks = 0; ks < 2; ks++) {
            uint32_t ah[4][4], al[4][4];
#pragma unroll
            for (int i = 0; i < 4; i++) {
                uint32_t arow = mw * 64 + i * 16 + r8 + (ts & 1) * 8;
                uint32_t aoff = arow * 80 + (ks * 16 + (ts >> 1) * 8) * 2;
                ldm4(ah[i], base + aoff);
                ldm4(al[i], base + OFF_AL * 2 + aoff);
            }
#pragma unroll
            for (int j = 0; j < 4; j++) {
                uint32_t brow = nw * 32 + j * 8 + rb;
                uint32_t boff = brow * 80 + (ks * 16 + tb * 8) * 2;
                uint32_t bh[2], bl[2];
                ldm2(bh, base + OFF_BH * 2 + boff);
                ldm2(bl, base + OFF_BL * 2 + boff);
#pragma unroll
                for (int i = 0; i < 4; i++) {
                    mma16816(accA[i][j], ah[i], bh);   // hi*hi
                    mma16816(accB[i][j], al[i], bh);   // lo'*hi
                    mma16816(accB[i][j], ah[i], bl);   // hi*lo'
                }
            }
        }
        __syncthreads();
    }

    // ---- epilogue: merge (acc = A + B/2048) and scatter into bin layout ----
    const float INV = 4.8828125e-4f;
#pragma unroll
    for (int i = 0; i < 4; i++) {
#pragma unroll
        for (int hf = 0; hf < 2; hf++) {
            int w = w0 + mw * 64 + i * 16 + q + hf * 8;
            int k = (h % 3) * 3 + (w % 3);
            size_t p   = (size_t)(h / 3) * 128 + (w / 3);
            size_t row = (size_t)(b * 9 + k) * LPOS + p;
            float* y1r = g_y1 + row * CIN;
            float* y2r = g_y2 + row * COUTB;
#pragma unroll
            for (int j = 0; j < 4; j++) {
                int co = nbase + nw * 32 + j * 8 + tq * 2;
                float2 v = make_float2(accA[i][j][hf * 2]     + accB[i][j][hf * 2]     * INV,
                                       accA[i][j][hf * 2 + 1] + accB[i][j][hf * 2 + 1] * INV);
                if (co < CIN) *(float2*)(y1r + co) = v;
                else          *(float2*)(y2r + co - CIN) = v;
            }
        }
    }
}

// =====================================================================
// stage 2: bin GEMM with split-K (proven)
// =====================================================================
__global__ void __launch_bounds__(256, 2) gemm_part_kernel()
{
    __shared__ __align__(16) float As[16 * 128];
    __shared__ __align__(16) float Bs[16 * 128];
    const int s = blockIdx.x, mt = blockIdx.y, bk = blockIdx.z;
    const int t = threadIdx.x, ogrp = t >> 4, igrp = t & 15;
    const float* __restrict__ A = g_y2 + (size_t)bk * LPOS * COUTB + mt * 128;
    const float* __restrict__ B = g_y1 + (size_t)bk * LPOS * CIN;
    unsigned long long acc[8][4];
#pragma unroll
    for (int oo = 0; oo < 8; oo++)
#pragma unroll
        for (int qq = 0; qq < 4; qq++) acc[oo][qq] = 0ull;
    const int pBase = s * (LPOS / 16);
    for (int pc = 0; pc < LPOS / 16; pc += 16) {
        const int p0 = pBase + pc;
#pragma unroll
        for (int u = 0; u < 2; u++) {
            int f = t + u * 256, row = f >> 5, col4 = (f & 31) << 2;
            *(float4*)&As[row * 128 + col4] = *(const float4*)&A[(size_t)(p0 + row) * COUTB + col4];
            *(float4*)&Bs[row * 128 + col4] = *(const float4*)&B[(size_t)(p0 + row) * CIN + col4];
        }
        __syncthreads();
#pragma unroll
        for (int k = 0; k < 16; k++) {
            float4 a0 = *(const float4*)&As[k * 128 + ogrp * 8];
            float4 a1 = *(const float4*)&As[k * 128 + ogrp * 8 + 4];
            const unsigned long long* bp = (const unsigned long long*)&Bs[k * 128 + igrp * 8];
            unsigned long long b0 = bp[0], b1 = bp[1], b2 = bp[2], b3 = bp[3];
            float av[8] = {a0.x, a0.y, a0.z, a0.w, a1.x, a1.y, a1.z, a1.w};
#pragma unroll
            for (int oo = 0; oo < 8; oo++) {
                unsigned long long ap = pack2(av[oo], av[oo]);
                acc[oo][0] = fma2(b0, ap, acc[oo][0]);
                acc[oo][1] = fma2(b1, ap, acc[oo][1]);
                acc[oo][2] = fma2(b2, ap, acc[oo][2]);
                acc[oo][3] = fma2(b3, ap, acc[oo][3]);
            }
        }
        __syncthreads();
    }
    float* dst = g_part + (size_t)((bk * 2 + mt) * 16 + s) * 16384;
#pragma unroll
    for (int oo = 0; oo < 8; oo++) {
        float2 q0 = unpack2(acc[oo][0]), q1 = unpack2(acc[oo][1]);
        float2 q2 = unpack2(acc[oo][2]), q3 = unpack2(acc[oo][3]);
        float* d = dst + (size_t)(ogrp * 8 + oo) * 128 + igrp * 8;
        *(float4*)d       = make_float4(q0.x, q0.y, q1.x, q1.y);
        *(float4*)(d + 4) = make_float4(q2.x, q2.y, q3.x, q3.y);
    }
}

// =====================================================================
// split-K reduce + softmax (proven)
// =====================================================================
__global__ void __launch_bounds__(128) softmax_kernel(float* __restrict__ out)
{
    const int bo = blockIdx.x, b = bo >> 8, o = bo & 255;
    const int mt = o >> 7, ol = o & 127, i = threadIdx.x;
    const float SCALE = 0.029462782549439476f;
    float lg[9];
#pragma unroll
    for (int k = 0; k < 9; k++) {
        const float* p = g_part + (size_t)(((b * 9 + k) * 2 + mt) * 16) * 16384 + (size_t)ol * 128 + i;
        float sum = 0.f;
#pragma unroll
        for (int s = 0; s < 16; s++) sum += p[(size_t)s * 16384];
        lg[k] = sum * SCALE;
    }
    float m = lg[0];
#pragma unroll
    for (int k = 1; k < 9; k++) m = fmaxf(m, lg[k]);
#pragma unroll
    for (int off = 16; off; off >>= 1) m = fmaxf(m, __shfl_xor_sync(0xffffffffu, m, off));
    __shared__ float smax[4];
    if ((i & 31) == 0) smax[i >> 5] = m;
    __syncthreads();
    m = fmaxf(fmaxf(smax[0], smax[1]), fmaxf(smax[2], smax[3]));
    float e[9], ls = 0.f;
#pragma unroll
    for (int k = 0; k < 9; k++) { e[k] = expf(lg[k] - m); ls += e[k]; }
#pragma unroll
    for (int off = 16; off; off >>= 1) ls += __shfl_xor_sync(0xffffffffu, ls, off);
    __shared__ float ssum[4];
    if ((i & 31) == 0) ssum[i >> 5] = ls;
    __syncthreads();
    ls = (ssum[0] + ssum[1]) + (ssum[2] + ssum[3]);
    float inv = 1.f / ls;
    float* dst = out + ((size_t)bo * 128 + i) * 9;
#pragma unroll
    for (int k = 0; k < 9; k++) dst[k] = e[k] * inv;
}

// =====================================================================
extern "C" void kernel_launch(void* const* d_in, const int* in_sizes, int n_in,
                              void* d_out, int out_size)
{
    const float* x  = (const float*)d_in[0];
    const float* w1 = (const float*)d_in[1];
    const float* w2 = (const float*)d_in[2];
    float* out = (float*)d_out;

    cudaFuncSetAttribute(conv_mma_kernel, cudaFuncAttributeMaxDynamicSharedMemorySize, SMEM_BYTES);

    prep_x_kernel<<<dim3((PADW + 31) / 32, PADW, NB * 4), dim3(32, 8)>>>(x);
    prep_w_kernel<<<(MTOT * KTOT + 255) / 256, 256>>>(w1, w2);
    conv_mma_kernel<<<dim3(3, 3, HW * NB), 256, SMEM_BYTES>>>();
    gemm_part_kernel<<<dim3(16, 2, 36), 256>>>();
    softmax_kernel<<<NB * COUTB, 128>>>(out);
}

// round 12
// speedup vs baseline: 2.9630x; 1.2537x over previous
#include <cuda_runtime.h>
#include <cuda_fp16.h>
#include <math.h>
#include <stdint.h>

#define CIN   128
#define COUTB 256
#define HW    384
#define LPOS  16384
#define NB    4
#define NTILE 36864            // 192*192 winograd tiles per image
#define NCO   384              // fused couts

// ---------------- static device scratch ----------------
__device__ __align__(16) float  g_y1[(size_t)NB * 9 * LPOS * CIN];
__device__ __align__(16) float  g_y2[(size_t)NB * 9 * LPOS * COUTB];
__device__ __align__(16) float  g_part[(size_t)36 * 2 * 16 * 128 * 128];
__device__ __align__(16) __half g_Vh[(size_t)NB * 16 * NTILE * CIN];   // 604 MB
__device__ __align__(16) __half g_Vl[(size_t)NB * 16 * NTILE * CIN];
__device__ __align__(16) __half g_Uh[(size_t)16 * NCO * CIN];
__device__ __align__(16) __half g_Ul[(size_t)16 * NCO * CIN];

// ---------------- helpers ----------------
__device__ __forceinline__ unsigned long long pack2(float x, float y) {
    unsigned long long r; asm("mov.b64 %0, {%1,%2};" : "=l"(r) : "f"(x), "f"(y)); return r;
}
__device__ __forceinline__ unsigned long long fma2(unsigned long long a, unsigned long long b, unsigned long long c) {
    unsigned long long d; asm("fma.rn.f32x2 %0, %1, %2, %3;" : "=l"(d) : "l"(a), "l"(b), "l"(c)); return d;
}
__device__ __forceinline__ float2 unpack2(unsigned long long v) {
    float2 f; asm("mov.b64 {%0,%1}, %2;" : "=f"(f.x), "=f"(f.y) : "l"(v)); return f;
}
__device__ __forceinline__ uint32_t s2u(const void* p) {
    uint32_t a; asm("{ .reg .u64 t; cvta.to.shared.u64 t, %1; cvt.u32.u64 %0, t; }" : "=r"(a) : "l"(p)); return a;
}
__device__ __forceinline__ void cpa16(uint32_t dst, const void* src) {
    asm volatile("cp.async.cg.shared.global [%0], [%1], 16;" :: "r"(dst), "l"(src));
}
__device__ __forceinline__ void ldm4(uint32_t* r, uint32_t addr) {
    asm volatile("ldmatrix.sync.aligned.m8n8.x4.shared.b16 {%0,%1,%2,%3}, [%4];"
        : "=r"(r[0]), "=r"(r[1]), "=r"(r[2]), "=r"(r[3]) : "r"(addr));
}
__device__ __forceinline__ void ldm2(uint32_t* r, uint32_t addr) {
    asm volatile("ldmatrix.sync.aligned.m8n8.x2.shared.b16 {%0,%1}, [%2];"
        : "=r"(r[0]), "=r"(r[1]) : "r"(addr));
}
__device__ __forceinline__ void mma16816(float* d, const uint32_t* a, const uint32_t* b) {
    asm volatile("mma.sync.aligned.m16n8k16.row.col.f32.f16.f16.f32 "
        "{%0,%1,%2,%3}, {%4,%5,%6,%7}, {%8,%9}, {%0,%1,%2,%3};"
        : "+f"(d[0]), "+f"(d[1]), "+f"(d[2]), "+f"(d[3])
        : "r"(a[0]), "r"(a[1]), "r"(a[2]), "r"(a[3]), "r"(b[0]), "r"(b[1]));
}

// =====================================================================
// K1: weight transform U = G g G^T, split into fp16 hi + 2048*lo limbs.
// Layout: g_U*[e][co][ci], e = r*4+c.
// =====================================================================
__global__ void prep_uw_kernel(const float* __restrict__ w1, const float* __restrict__ w2)
{
    int idx = blockIdx.x * 256 + threadIdx.x;      // co*128 + ci, 49152 total
    if (idx >= NCO * CIN) return;
    int co = idx >> 7, ci = idx & 127;
    const float* src = (co < CIN) ? (w1 + ((size_t)co * CIN + ci) * 9)
                                  : (w2 + ((size_t)(co - CIN) * CIN + ci) * 9);
    float g[3][3];
#pragma unroll
    for (int r = 0; r < 3; r++)
#pragma unroll
        for (int c = 0; c < 3; c++) g[r][c] = src[r * 3 + c];

    float tr[4][3];
#pragma unroll
    for (int c = 0; c < 3; c++) {
        tr[0][c] = g[0][c];
        tr[1][c] = 0.5f * (g[0][c] + g[1][c] + g[2][c]);
        tr[2][c] = 0.5f * (g[0][c] - g[1][c] + g[2][c]);
        tr[3][c] = g[2][c];
    }
#pragma unroll
    for (int r = 0; r < 4; r++) {
        float u0 = tr[r][0];
        float u1 = 0.5f * (tr[r][0] + tr[r][1] + tr[r][2]);
        float u2 = 0.5f * (tr[r][0] - tr[r][1] + tr[r][2]);
        float u3 = tr[r][2];
        float uu[4] = {u0, u1, u2, u3};
#pragma unroll
        for (int c = 0; c < 4; c++) {
            int e = r * 4 + c;
            __half hi = __float2half_rn(uu[c]);
            __half lo = __float2half_rn((uu[c] - __half2float(hi)) * 2048.0f);
            g_Uh[(size_t)e * (NCO * CIN) + idx] = hi;
            g_Ul[(size_t)e * (NCO * CIN) + idx] = lo;
        }
    }
}

// =====================================================================
// K2: input transform V = B^T d B per 4x4 window (stride 2, pad 1).
// Block: 16 tiles in x * 1 tile-row * 32 ci. Output [b][e][tile][ci].
// =====================================================================
__global__ void transform_x_kernel(const float* __restrict__ x)
{
    __shared__ float st[4][34][33];     // [r][c][ci] (ci innermost, conflict-free)
    const int bx = blockIdx.x;          // 0..11 (16 tiles each)
    const int ty = blockIdx.y;          // 0..191
    const int cic = blockIdx.z & 3, b = blockIdx.z >> 2;
    const int t = threadIdx.x, l = t & 31, wrp = t >> 5;

    // load 4 rows x 34 cols x 32 ci (coalesced along w)
#pragma unroll
    for (int it = 0; it < 4; it++) {
        int ci_l = it * 8 + wrp;
        const float* xp = x + ((size_t)(b * CIN + cic * 32 + ci_l)) * HW * HW;
#pragma unroll
        for (int r = 0; r < 4; r++) {
            int h = 2 * ty - 1 + r;
            for (int c = l; c < 34; c += 32) {
                int w = bx * 32 - 1 + c;
                float v = 0.f;
                if ((unsigned)h < HW && (unsigned)w < HW) v = xp[(size_t)h * HW + w];
                st[r][c][ci_l] = v;
            }
        }
    }
    __syncthreads();

    const int ci_l = t & 31, tl = t >> 5;
#pragma unroll
    for (int pass = 0; pass < 2; pass++) {
        int txl = pass * 8 + tl;
        int cb  = 2 * txl;
        float d[4][4];
#pragma unroll
        for (int r = 0; r < 4; r++)
#pragma unroll
            for (int c = 0; c < 4; c++) d[r][c] = st[r][cb + c][ci_l];

        float tm[4][4];
#pragma unroll
        for (int c = 0; c < 4; c++) {
            tm[0][c] = d[0][c] - d[2][c];
            tm[1][c] = d[1][c] + d[2][c];
            tm[2][c] = d[2][c] - d[1][c];
            tm[3][c] = d[1][c] - d[3][c];
        }
        size_t tile = (size_t)ty * 192 + bx * 16 + txl;
#pragma unroll
        for (int r = 0; r < 4; r++) {
            float v0 = tm[r][0] - tm[r][2];
            float v1 = tm[r][1] + tm[r][2];
            float v2 = tm[r][2] - tm[r][1];
            float v3 = tm[r][1] - tm[r][3];
            float vv[4] = {v0, v1, v2, v3};
#pragma unroll
            for (int c = 0; c < 4; c++) {
                int e = r * 4 + c;
                size_t off = ((size_t)(b * 16 + e) * NTILE + tile) * CIN + cic * 32 + ci_l;
                __half hi = __float2half_rn(vv[c]);
                g_Vh[off] = hi;
                g_Vl[off] = __float2half_rn((vv[c] - __half2float(hi)) * 2048.0f);
            }
        }
    }
}

// =====================================================================
// K3: 16 batched GEMMs M_e[co][tile] (K=128 ci), split-FP16 3-product,
// output transform y = A^T M A fused in registers, scatter to bin layout.
// CTA: co 128 x tiles 32, loop e 0..15, double-buffered smem.
// Warps 4(m) x 2(n): warp = co32 x tile16. Row stride 136 halves (272B).
// =====================================================================
#define W_SA   17408               // 128*136 halves (one A limb)
#define W_SB   4352                // 32*136
#define W_AL   17408
#define W_BH   34816
#define W_BL   39168
#define W_STG  43520               // halves per stage
#define W_SMEM (2 * W_STG * 2)     // 174080 bytes

__global__ void __launch_bounds__(256, 1) wino_gemm_kernel()
{
    extern __shared__ __half sw[];
    const int t = threadIdx.x, l = t & 31, wrp = t >> 5;
    const int mw = wrp & 3, nw = wrp >> 2;
    const int q = l >> 2, tq = l & 3;
    const int tb = blockIdx.x, cob = blockIdx.y, b = blockIdx.z;
    const uint32_t smb = s2u(sw);

    float yac[2][2][4][4];
#pragma unroll
    for (int i = 0; i < 2; i++)
#pragma unroll
        for (int j = 0; j < 2; j++)
#pragma unroll
            for (int d = 0; d < 4; d++)
#pragma unroll
                for (int uv = 0; uv < 4; uv++) yac[i][j][d][uv] = 0.f;

    auto load_e = [&](int e, int buf) {
        const uint32_t base = smb + buf * (W_STG * 2);
        const __half* Uh = g_Uh + (size_t)e * (NCO * CIN) + (size_t)cob * 128 * CIN;
        const __half* Ul = g_Ul + (size_t)e * (NCO * CIN) + (size_t)cob * 128 * CIN;
#pragma unroll
        for (int i = 0; i < 8; i++) {
            int id = t + i * 256;            // 0..2047
            int row = id >> 4, kc = id & 15;
            uint32_t o = (row * 136 + kc * 8) * 2;
            cpa16(base + o,           Uh + (size_t)row * CIN + kc * 8);
            cpa16(base + W_AL * 2 + o, Ul + (size_t)row * CIN + kc * 8);
        }
        const __half* Vh = g_Vh + ((size_t)(b * 16 + e) * NTILE + (size_t)tb * 32) * CIN;
        const __half* Vl = g_Vl + ((size_t)(b * 16 + e) * NTILE + (size_t)tb * 32) * CIN;
#pragma unroll
        for (int i = 0; i < 2; i++) {
            int id = t + i * 256;            // 0..511
            int row = id >> 4, kc = id & 15;
            uint32_t o = (row * 136 + kc * 8) * 2;
            cpa16(base + W_BH * 2 + o, Vh + (size_t)row * CIN + kc * 8);
            cpa16(base + W_BL * 2 + o, Vl + (size_t)row * CIN + kc * 8);
        }
        asm volatile("cp.async.commit_group;" ::: "memory");
    };

    const float AT0[4] = {1.f, 1.f, 1.f, 0.f};
    const float AT1[4] = {0.f, 1.f, -1.f, -1.f};
    const float INV = 4.8828125e-4f;

    load_e(0, 0);

#pragma unroll 1
    for (int e = 0; e < 16; e++) {
        const int buf = e & 1;
        if (e < 15) {
            load_e(e + 1, buf ^ 1);
            asm volatile("cp.async.wait_group 1;" ::: "memory");
        } else {
            asm volatile("cp.async.wait_group 0;" ::: "memory");
        }
        __syncthreads();

        const uint32_t base = smb + buf * (W_STG * 2);
        const int r8 = l & 7, tt = l >> 3, tb2 = (l >> 3) & 1;

        float mA[2][2][4], mB[2][2][4];
#pragma unroll
        for (int i = 0; i < 2; i++)
#pragma unroll
            for (int j = 0; j < 2; j++)
#pragma unroll
                for (int d = 0; d < 4; d++) { mA[i][j][d] = 0.f; mB[i][j][d] = 0.f; }

#pragma unroll
        for (int ks = 0; ks < 8; ks++) {
            uint32_t ah[2][4], al[2][4];
#pragma unroll
            for (int i = 0; i < 2; i++) {
                uint32_t arow = mw * 32 + i * 16 + (tt & 1) * 8 + r8;
                uint32_t aoff = arow * 272 + (ks * 16 + (tt >> 1) * 8) * 2;
                ldm4(ah[i], base + aoff);
                ldm4(al[i], base + W_AL * 2 + aoff);
            }
            uint32_t bh[2][2], bl[2][2];
#pragma unroll
            for (int j = 0; j < 2; j++) {
                uint32_t brow = nw * 16 + j * 8 + r8;
                uint32_t boff = brow * 272 + (ks * 16 + tb2 * 8) * 2;
                ldm2(bh[j], base + W_BH * 2 + boff);
                ldm2(bl[j], base + W_BL * 2 + boff);
            }
#pragma unroll
            for (int i = 0; i < 2; i++)
#pragma unroll
                for (int j = 0; j < 2; j++) {
                    mma16816(mA[i][j], ah[i], bh[j]);
                    mma16816(mB[i][j], al[i], bh[j]);
                    mma16816(mB[i][j], ah[i], bl[j]);
                }
        }

        // output-transform accumulate: y[u][v] += AT0/1[er]*AT0/1[ec]*m
        const int er = e >> 2, ec = e & 3;
        const float u0 = AT0[er], u1 = AT1[er], v0 = AT0[ec], v1 = AT1[ec];
#pragma unroll
        for (int i = 0; i < 2; i++)
#pragma unroll
            for (int j = 0; j < 2; j++)
#pragma unroll
                for (int d = 0; d < 4; d++) {
                    float m = mA[i][j][d] + mB[i][j][d] * INV;
                    yac[i][j][d][0] += u0 * v0 * m;
                    yac[i][j][d][1] += u0 * v1 * m;
                    yac[i][j][d][2] += u1 * v0 * m;
                    yac[i][j][d][3] += u1 * v1 * m;
                }
        __syncthreads();
    }

    // ---- scatter into bin layout (fp32, same as before) ----
#pragma unroll
    for (int i = 0; i < 2; i++) {
#pragma unroll
        for (int j = 0; j < 2; j++) {
#pragma unroll
            for (int d = 0; d < 4; d++) {
                int co = cob * 128 + mw * 32 + i * 16 + (d >> 1) * 8 + q;
                int tile = tb * 32 + nw * 16 + j * 8 + tq * 2 + (d & 1);
                int tyy = tile / 192, txx = tile - tyy * 192;
#pragma unroll
                for (int u = 0; u < 2; u++) {
#pragma unroll
                    for (int v = 0; v < 2; v++) {
                        int h = 2 * tyy + u, w = 2 * txx + v;
                        int k = (h % 3) * 3 + (w % 3);
                        size_t p   = (size_t)(h / 3) * 128 + (w / 3);
                        size_t row = (size_t)(b * 9 + k) * LPOS + p;
                        float val = yac[i][j][d][u * 2 + v];
                        if (co < CIN) g_y1[row * CIN + co] = val;
                        else          g_y2[row * COUTB + co - CIN] = val;
                    }
                }
            }
        }
    }
}

// =====================================================================
// stage 2: bin GEMM with split-K (proven, unchanged)
// =====================================================================
__global__ void __launch_bounds__(256, 2) gemm_part_kernel()
{
    __shared__ __align__(16) float As[16 * 128];
    __shared__ __align__(16) float Bs[16 * 128];
    const int s = blockIdx.x, mt = blockIdx.y, bk = blockIdx.z;
    const int t = threadIdx.x, ogrp = t >> 4, igrp = t & 15;
    const float* __restrict__ A = g_y2 + (size_t)bk * LPOS * COUTB + mt * 128;
    const float* __restrict__ B = g_y1 + (size_t)bk * LPOS * CIN;
    unsigned long long acc[8][4];
#pragma unroll
    for (int oo = 0; oo < 8; oo++)
#pragma unroll
        for (int qq = 0; qq < 4; qq++) acc[oo][qq] = 0ull;
    const int pBase = s * (LPOS / 16);
    for (int pc = 0; pc < LPOS / 16; pc += 16) {
        const int p0 = pBase + pc;
#pragma unroll
        for (int u = 0; u < 2; u++) {
            int f = t + u * 256, row = f >> 5, col4 = (f & 31) << 2;
            *(float4*)&As[row * 128 + col4] = *(const float4*)&A[(size_t)(p0 + row) * COUTB + col4];
            *(float4*)&Bs[row * 128 + col4] = *(const float4*)&B[(size_t)(p0 + row) * CIN + col4];
        }
        __syncthreads();
#pragma unroll
        for (int k = 0; k < 16; k++) {
            float4 a0 = *(const float4*)&As[k * 128 + ogrp * 8];
            float4 a1 = *(const float4*)&As[k * 128 + ogrp * 8 + 4];
            const unsigned long long* bp = (const unsigned long long*)&Bs[k * 128 + igrp * 8];
            unsigned long long b0 = bp[0], b1 = bp[1], b2 = bp[2], b3 = bp[3];
            float av[8] = {a0.x, a0.y, a0.z, a0.w, a1.x, a1.y, a1.z, a1.w};
#pragma unroll
            for (int oo = 0; oo < 8; oo++) {
                unsigned long long ap = pack2(av[oo], av[oo]);
                acc[oo][0] = fma2(b0, ap, acc[oo][0]);
                acc[oo][1] = fma2(b1, ap, acc[oo][1]);
                acc[oo][2] = fma2(b2, ap, acc[oo][2]);
                acc[oo][3] = fma2(b3, ap, acc[oo][3]);
            }
        }
        __syncthreads();
    }
    float* dst = g_part + (size_t)((bk * 2 + mt) * 16 + s) * 16384;
#pragma unroll
    for (int oo = 0; oo < 8; oo++) {
        float2 q0 = unpack2(acc[oo][0]), q1 = unpack2(acc[oo][1]);
        float2 q2 = unpack2(acc[oo][2]), q3 = unpack2(acc[oo][3]);
        float* d = dst + (size_t)(ogrp * 8 + oo) * 128 + igrp * 8;
        *(float4*)d       = make_float4(q0.x, q0.y, q1.x, q1.y);
        *(float4*)(d + 4) = make_float4(q2.x, q2.y, q3.x, q3.y);
    }
}

// =====================================================================
// split-K reduce + softmax (proven, unchanged)
// =====================================================================
__global__ void __launch_bounds__(128) softmax_kernel(float* __restrict__ out)
{
    const int bo = blockIdx.x, b = bo >> 8, o = bo & 255;
    const int mt = o >> 7, ol = o & 127, i = threadIdx.x;
    const float SCALE = 0.029462782549439476f;
    float lg[9];
#pragma unroll
    for (int k = 0; k < 9; k++) {
        const float* p = g_part + (size_t)(((b * 9 + k) * 2 + mt) * 16) * 16384 + (size_t)ol * 128 + i;
        float sum = 0.f;
#pragma unroll
        for (int s = 0; s < 16; s++) sum += p[(size_t)s * 16384];
        lg[k] = sum * SCALE;
    }
    float m = lg[0];
#pragma unroll
    for (int k = 1; k < 9; k++) m = fmaxf(m, lg[k]);
#pragma unroll
    for (int off = 16; off; off >>= 1) m = fmaxf(m, __shfl_xor_sync(0xffffffffu, m, off));
    __shared__ float smax[4];
    if ((i & 31) == 0) smax[i >> 5] = m;
    __syncthreads();
    m = fmaxf(fmaxf(smax[0], smax[1]), fmaxf(smax[2], smax[3]));
    float e[9], ls = 0.f;
#pragma unroll
    for (int k = 0; k < 9; k++) { e[k] = expf(lg[k] - m); ls += e[k]; }
#pragma unroll
    for (int off = 16; off; off >>= 1) ls += __shfl_xor_sync(0xffffffffu, ls, off);
    __shared__ float ssum[4];
    if ((i & 31) == 0) ssum[i >> 5] = ls;
    __syncthreads();
    ls = (ssum[0] + ssum[1]) + (ssum[2] + ssum[3]);
    float inv = 1.f / ls;
    float* dst = out + ((size_t)bo * 128 + i) * 9;
#pragma unroll
    for (int k = 0; k < 9; k++) dst[k] = e[k] * inv;
}

// =====================================================================
extern "C" void kernel_launch(void* const* d_in, const int* in_sizes, int n_in,
                              void* d_out, int out_size)
{
    const float* x  = (const float*)d_in[0];
    const float* w1 = (const float*)d_in[1];
    const float* w2 = (const float*)d_in[2];
    float* out = (float*)d_out;

    cudaFuncSetAttribute(wino_gemm_kernel, cudaFuncAttributeMaxDynamicSharedMemorySize, W_SMEM);

    prep_uw_kernel<<<(NCO * CIN + 255) / 256, 256>>>(w1, w2);
    transform_x_kernel<<<dim3(12, 192, 16), 256>>>(x);
    wino_gemm_kernel<<<dim3(NTILE / 32, 3, NB), 256, W_SMEM>>>();
    gemm_part_kernel<<<dim3(16, 2, 36), 256>>>();
    softmax_kernel<<<NB * COUTB, 128>>>(out);
}

// round 13
// speedup vs baseline: 3.1660x; 1.0685x over previous
#include <cuda_runtime.h>
#include <cuda_fp16.h>
#include <math.h>
#include <stdint.h>

#define CIN   128
#define COUTB 256
#define HW    384
#define LPOS  16384
#define NB    4
#define NTILE 36864            // 192*192 winograd tiles per image
#define NCO   384              // fused couts

// ---------------- static device scratch ----------------
__device__ __align__(16) float  g_part[(size_t)36 * 2 * 8 * 128 * 128];
__device__ __align__(16) __half g_y1h[(size_t)NB * 9 * LPOS * CIN];
__device__ __align__(16) __half g_y1l[(size_t)NB * 9 * LPOS * CIN];
__device__ __align__(16) __half g_y2h[(size_t)NB * 9 * LPOS * COUTB];
__device__ __align__(16) __half g_y2l[(size_t)NB * 9 * LPOS * COUTB];
__device__ __align__(16) __half g_Vh[(size_t)NB * 16 * NTILE * CIN];
__device__ __align__(16) __half g_Vl[(size_t)NB * 16 * NTILE * CIN];
__device__ __align__(16) __half g_Uh[(size_t)16 * NCO * CIN];
__device__ __align__(16) __half g_Ul[(size_t)16 * NCO * CIN];

// ---------------- helpers ----------------
__device__ __forceinline__ uint32_t s2u(const void* p) {
    uint32_t a; asm("{ .reg .u64 t; cvta.to.shared.u64 t, %1; cvt.u32.u64 %0, t; }" : "=r"(a) : "l"(p)); return a;
}
__device__ __forceinline__ void cpa16(uint32_t dst, const void* src) {
    asm volatile("cp.async.cg.shared.global [%0], [%1], 16;" :: "r"(dst), "l"(src));
}
__device__ __forceinline__ void ldm4(uint32_t* r, uint32_t addr) {
    asm volatile("ldmatrix.sync.aligned.m8n8.x4.shared.b16 {%0,%1,%2,%3}, [%4];"
        : "=r"(r[0]), "=r"(r[1]), "=r"(r[2]), "=r"(r[3]) : "r"(addr));
}
__device__ __forceinline__ void ldm4t(uint32_t* r, uint32_t addr) {
    asm volatile("ldmatrix.sync.aligned.m8n8.x4.trans.shared.b16 {%0,%1,%2,%3}, [%4];"
        : "=r"(r[0]), "=r"(r[1]), "=r"(r[2]), "=r"(r[3]) : "r"(addr));
}
__device__ __forceinline__ void mma16816(float* d, const uint32_t* a, const uint32_t* b) {
    asm volatile("mma.sync.aligned.m16n8k16.row.col.f32.f16.f16.f32 "
        "{%0,%1,%2,%3}, {%4,%5,%6,%7}, {%8,%9}, {%0,%1,%2,%3};"
        : "+f"(d[0]), "+f"(d[1]), "+f"(d[2]), "+f"(d[3])
        : "r"(a[0]), "r"(a[1]), "r"(a[2]), "r"(a[3]), "r"(b[0]), "r"(b[1]));
}

// =====================================================================
// K1: weight transform U = G g G^T, fp16 hi + 2048*lo limbs. [e][co][ci]
// =====================================================================
__global__ void prep_uw_kernel(const float* __restrict__ w1, const float* __restrict__ w2)
{
    int idx = blockIdx.x * 256 + threadIdx.x;
    if (idx >= NCO * CIN) return;
    int co = idx >> 7, ci = idx & 127;
    const float* src = (co < CIN) ? (w1 + ((size_t)co * CIN + ci) * 9)
                                  : (w2 + ((size_t)(co - CIN) * CIN + ci) * 9);
    float g[3][3];
#pragma unroll
    for (int r = 0; r < 3; r++)
#pragma unroll
        for (int c = 0; c < 3; c++) g[r][c] = src[r * 3 + c];
    float tr[4][3];
#pragma unroll
    for (int c = 0; c < 3; c++) {
        tr[0][c] = g[0][c];
        tr[1][c] = 0.5f * (g[0][c] + g[1][c] + g[2][c]);
        tr[2][c] = 0.5f * (g[0][c] - g[1][c] + g[2][c]);
        tr[3][c] = g[2][c];
    }
#pragma unroll
    for (int r = 0; r < 4; r++) {
        float uu[4];
        uu[0] = tr[r][0];
        uu[1] = 0.5f * (tr[r][0] + tr[r][1] + tr[r][2]);
        uu[2] = 0.5f * (tr[r][0] - tr[r][1] + tr[r][2]);
        uu[3] = tr[r][2];
#pragma unroll
        for (int c = 0; c < 4; c++) {
            int e = r * 4 + c;
            __half hi = __float2half_rn(uu[c]);
            __half lo = __float2half_rn((uu[c] - __half2float(hi)) * 2048.0f);
            g_Uh[(size_t)e * (NCO * CIN) + idx] = hi;
            g_Ul[(size_t)e * (NCO * CIN) + idx] = lo;
        }
    }
}

// =====================================================================
// K2: input transform V = B^T d B per 4x4 window (stride 2, pad 1).
// =====================================================================
__global__ void transform_x_kernel(const float* __restrict__ x)
{
    __shared__ float st[4][34][33];
    const int bx = blockIdx.x;
    const int ty = blockIdx.y;
    const int cic = blockIdx.z & 3, b = blockIdx.z >> 2;
    const int t = threadIdx.x, l = t & 31, wrp = t >> 5;

#pragma unroll
    for (int it = 0; it < 4; it++) {
        int ci_l = it * 8 + wrp;
        const float* xp = x + ((size_t)(b * CIN + cic * 32 + ci_l)) * HW * HW;
#pragma unroll
        for (int r = 0; r < 4; r++) {
            int h = 2 * ty - 1 + r;
            for (int c = l; c < 34; c += 32) {
                int w = bx * 32 - 1 + c;
                float v = 0.f;
                if ((unsigned)h < HW && (unsigned)w < HW) v = xp[(size_t)h * HW + w];
                st[r][c][ci_l] = v;
            }
        }
    }
    __syncthreads();

    const int ci_l = t & 31, tl = t >> 5;
#pragma unroll
    for (int pass = 0; pass < 2; pass++) {
        int txl = pass * 8 + tl;
        int cb  = 2 * txl;
        float d[4][4];
#pragma unroll
        for (int r = 0; r < 4; r++)
#pragma unroll
            for (int c = 0; c < 4; c++) d[r][c] = st[r][cb + c][ci_l];
        float tm[4][4];
#pragma unroll
        for (int c = 0; c < 4; c++) {
            tm[0][c] = d[0][c] - d[2][c];
            tm[1][c] = d[1][c] + d[2][c];
            tm[2][c] = d[2][c] - d[1][c];
            tm[3][c] = d[1][c] - d[3][c];
        }
        size_t tile = (size_t)ty * 192 + bx * 16 + txl;
#pragma unroll
        for (int r = 0; r < 4; r++) {
            float vv[4];
            vv[0] = tm[r][0] - tm[r][2];
            vv[1] = tm[r][1] + tm[r][2];
            vv[2] = tm[r][2] - tm[r][1];
            vv[3] = tm[r][1] - tm[r][3];
#pragma unroll
            for (int c = 0; c < 4; c++) {
                int e = r * 4 + c;
                size_t off = ((size_t)(b * 16 + e) * NTILE + tile) * CIN + cic * 32 + ci_l;
                __half hi = __float2half_rn(vv[c]);
                g_Vh[off] = hi;
                g_Vl[off] = __float2half_rn((vv[c] - __half2float(hi)) * 2048.0f);
            }
        }
    }
}

// =====================================================================
// K3: winograd GEMM + fused output transform, scatter as half limbs.
// CTA: co 128 x tiles 32, loop e 0..15. Warps 4(m) x 2(n) = 32co x 16tile.
// =====================================================================
#define W_AL   17408               // halves: 128*136
#define W_BH   34816
#define W_BL   39168
#define W_STG  43520
#define W_SMEM (2 * W_STG * 2)

__global__ void __launch_bounds__(256, 1) wino_gemm_kernel()
{
    extern __shared__ __half sw[];
    const int t = threadIdx.x, l = t & 31, wrp = t >> 5;
    const int mw = wrp & 3, nw = wrp >> 2;
    const int q = l >> 2, tq = l & 3;
    const int tb = blockIdx.x, cob = blockIdx.y, b = blockIdx.z;
    const uint32_t smb = s2u(sw);

    float yac[2][2][4][4];
#pragma unroll
    for (int i = 0; i < 2; i++)
#pragma unroll
        for (int j = 0; j < 2; j++)
#pragma unroll
            for (int d = 0; d < 4; d++)
#pragma unroll
                for (int uv = 0; uv < 4; uv++) yac[i][j][d][uv] = 0.f;

    auto load_e = [&](int e, int buf) {
        const uint32_t base = smb + buf * (W_STG * 2);
        const __half* Uh = g_Uh + (size_t)e * (NCO * CIN) + (size_t)cob * 128 * CIN;
        const __half* Ul = g_Ul + (size_t)e * (NCO * CIN) + (size_t)cob * 128 * CIN;
#pragma unroll
        for (int i = 0; i < 8; i++) {
            int id = t + i * 256;
            int row = id >> 4, kc = id & 15;
            uint32_t o = (row * 136 + kc * 8) * 2;
            cpa16(base + o,            Uh + (size_t)row * CIN + kc * 8);
            cpa16(base + W_AL * 2 + o, Ul + (size_t)row * CIN + kc * 8);
        }
        const __half* Vh = g_Vh + ((size_t)(b * 16 + e) * NTILE + (size_t)tb * 32) * CIN;
        const __half* Vl = g_Vl + ((size_t)(b * 16 + e) * NTILE + (size_t)tb * 32) * CIN;
#pragma unroll
        for (int i = 0; i < 2; i++) {
            int id = t + i * 256;
            int row = id >> 4, kc = id & 15;
            uint32_t o = (row * 136 + kc * 8) * 2;
            cpa16(base + W_BH * 2 + o, Vh + (size_t)row * CIN + kc * 8);
            cpa16(base + W_BL * 2 + o, Vl + (size_t)row * CIN + kc * 8);
        }
        asm volatile("cp.async.commit_group;" ::: "memory");
    };

    const float AT0[4] = {1.f, 1.f, 1.f, 0.f};
    const float AT1[4] = {0.f, 1.f, -1.f, -1.f};
    const float INV = 4.8828125e-4f;

    load_e(0, 0);

#pragma unroll 1
    for (int e = 0; e < 16; e++) {
        const int buf = e & 1;
        if (e < 15) {
            load_e(e + 1, buf ^ 1);
            asm volatile("cp.async.wait_group 1;" ::: "memory");
        } else {
            asm volatile("cp.async.wait_group 0;" ::: "memory");
        }
        __syncthreads();

        const uint32_t base = smb + buf * (W_STG * 2);
        const int r8 = l & 7, tt = l >> 3;

        float mA[2][2][4], mB[2][2][4];
#pragma unroll
        for (int i = 0; i < 2; i++)
#pragma unroll
            for (int j = 0; j < 2; j++)
#pragma unroll
                for (int d = 0; d < 4; d++) { mA[i][j][d] = 0.f; mB[i][j][d] = 0.f; }

#pragma unroll
        for (int ks = 0; ks < 8; ks++) {
            uint32_t ah[2][4], al[2][4];
#pragma unroll
            for (int i = 0; i < 2; i++) {
                uint32_t arow = mw * 32 + i * 16 + (tt & 1) * 8 + r8;
                uint32_t aoff = arow * 272 + (ks * 16 + (tt >> 1) * 8) * 2;
                ldm4(ah[i], base + aoff);
                ldm4(al[i], base + W_AL * 2 + aoff);
            }
            // B: one ldm4 per limb covers n16 x k16 (matrices n0k0,n0k8,n8k0,n8k8)
            uint32_t bh4[4], bl4[4];
            {
                uint32_t brow = nw * 16 + (tt >> 1) * 8 + r8;
                uint32_t boff = brow * 272 + (ks * 16 + (tt & 1) * 8) * 2;
                ldm4(bh4, base + W_BH * 2 + boff);
                ldm4(bl4, base + W_BL * 2 + boff);
            }
#pragma unroll
            for (int i = 0; i < 2; i++)
#pragma unroll
                for (int j = 0; j < 2; j++) {
                    mma16816(mA[i][j], ah[i], bh4 + j * 2);
                    mma16816(mB[i][j], al[i], bh4 + j * 2);
                    mma16816(mB[i][j], ah[i], bl4 + j * 2);
                }
        }

        const int er = e >> 2, ec = e & 3;
        const float u0 = AT0[er], u1 = AT1[er], v0 = AT0[ec], v1 = AT1[ec];
#pragma unroll
        for (int i = 0; i < 2; i++)
#pragma unroll
            for (int j = 0; j < 2; j++)
#pragma unroll
                for (int d = 0; d < 4; d++) {
                    float m = mA[i][j][d] + mB[i][j][d] * INV;
                    yac[i][j][d][0] += u0 * v0 * m;
                    yac[i][j][d][1] += u0 * v1 * m;
                    yac[i][j][d][2] += u1 * v0 * m;
                    yac[i][j][d][3] += u1 * v1 * m;
                }
        __syncthreads();
    }

    // ---- scatter into bin layout as fp16 hi/lo limbs ----
#pragma unroll
    for (int i = 0; i < 2; i++) {
#pragma unroll
        for (int j = 0; j < 2; j++) {
#pragma unroll
            for (int d = 0; d < 4; d++) {
                int co = cob * 128 + mw * 32 + i * 16 + (d >> 1) * 8 + q;
                int tile = tb * 32 + nw * 16 + j * 8 + tq * 2 + (d & 1);
                int tyy = tile / 192, txx = tile - tyy * 192;
#pragma unroll
                for (int u = 0; u < 2; u++) {
#pragma unroll
                    for (int v = 0; v < 2; v++) {
                        int h = 2 * tyy + u, w = 2 * txx + v;
                        int k = (h % 3) * 3 + (w % 3);
                        size_t p   = (size_t)(h / 3) * 128 + (w / 3);
                        size_t row = (size_t)(b * 9 + k) * LPOS + p;
                        float val = yac[i][j][d][u * 2 + v];
                        __half hi = __float2half_rn(val);
                        __half lo = __float2half_rn((val - __half2float(hi)) * 2048.0f);
                        if (co < CIN) {
                            g_y1h[row * CIN + co] = hi;
                            g_y1l[row * CIN + co] = lo;
                        } else {
                            g_y2h[row * COUTB + co - CIN] = hi;
                            g_y2l[row * COUTB + co - CIN] = lo;
                        }
                    }
                }
            }
        }
    }
}

// =====================================================================
// stage 2: bin GEMM on split-FP16 mma. C[o128][i128], K=16384 split 8.
// CTA 512 thr, 16 warps (4m x 4n), warp 32o x 32i. K-chunk 32 staged.
// Both operands [p][c] -> ldmatrix.x4.trans fragments.
// =====================================================================
#define G2_AL  4352                // halves: 32*136
#define G2_BH  8704
#define G2_BL  13056
#define G2_STG 17408
#define G2_SMEM (2 * G2_STG * 2)   // 69632 bytes

__global__ void __launch_bounds__(512) gemm2_kernel()
{
    extern __shared__ __half s2[];
    const int t = threadIdx.x, l = t & 31, wrp = t >> 5;
    const int mw = wrp & 3, nw = wrp >> 2;
    const int q = l >> 2, tq = l & 3;
    const int s = blockIdx.x, mt = blockIdx.y, bk = blockIdx.z;
    const uint32_t smb = s2u(s2);

    const __half* __restrict__ Ah = g_y2h + (size_t)bk * LPOS * COUTB + mt * 128;
    const __half* __restrict__ Al = g_y2l + (size_t)bk * LPOS * COUTB + mt * 128;
    const __half* __restrict__ Bh = g_y1h + (size_t)bk * LPOS * CIN;
    const __half* __restrict__ Bl = g_y1l + (size_t)bk * LPOS * CIN;

    float accA[2][4][4], accB[2][4][4];
#pragma unroll
    for (int i = 0; i < 2; i++)
#pragma unroll
        for (int j = 0; j < 4; j++)
#pragma unroll
            for (int r = 0; r < 4; r++) { accA[i][j][r] = 0.f; accB[i][j][r] = 0.f; }

    const int row = t >> 4, kc = t & 15;        // 512 threads = 32 rows x 16 cols16B
    const uint32_t so = (row * 136 + kc * 8) * 2;

    auto load_chunk = [&](int p0, int buf) {
        const uint32_t base = smb + buf * (G2_STG * 2);
        size_t ga = (size_t)(p0 + row) * COUTB + kc * 8;
        size_t gb = (size_t)(p0 + row) * CIN + kc * 8;
        cpa16(base + so,             Ah + ga);
        cpa16(base + G2_AL * 2 + so, Al + ga);
        cpa16(base + G2_BH * 2 + so, Bh + gb);
        cpa16(base + G2_BL * 2 + so, Bl + gb);
        asm volatile("cp.async.commit_group;" ::: "memory");
    };

    const int pBase = s * (LPOS / 8);           // 2048 positions per split
    load_chunk(pBase, 0);

    for (int pc = 0; pc < 64; pc++) {
        const int buf = pc & 1;
        if (pc < 63) {
            load_chunk(pBase + (pc + 1) * 32, buf ^ 1);
            asm volatile("cp.async.wait_group 1;" ::: "memory");
        } else {
            asm volatile("cp.async.wait_group 0;" ::: "memory");
        }
        __syncthreads();

        const uint32_t base = smb + buf * (G2_STG * 2);
        const int r8 = l & 7, g = l >> 3;

#pragma unroll
        for (int ks = 0; ks < 2; ks++) {
            // A frags (trans): rows = p, cols = o
            uint32_t ah[2][4], al[2][4];
#pragma unroll
            for (int i = 0; i < 2; i++) {
                uint32_t aoff = ((ks * 16 + (g >> 1) * 8 + r8) * 136
                               + mw * 32 + i * 16 + (g & 1) * 8) * 2;
                ldm4t(ah[i], base + aoff);
                ldm4t(al[i], base + G2_AL * 2 + aoff);
            }
            // B frags (trans): rows = p, cols = i ; one ldm4 covers n16 x k16
            uint32_t bh[2][4], bl[2][4];
#pragma unroll
            for (int jp = 0; jp < 2; jp++) {
                uint32_t boff = ((ks * 16 + (g & 1) * 8 + r8) * 136
                               + nw * 32 + jp * 16 + (g >> 1) * 8) * 2;
                ldm4t(bh[jp], base + G2_BH * 2 + boff);
                ldm4t(bl[jp], base + G2_BL * 2 + boff);
            }
#pragma unroll
            for (int i = 0; i < 2; i++)
#pragma unroll
                for (int j = 0; j < 4; j++) {
                    const uint32_t* bhj = bh[j >> 1] + (j & 1) * 2;
                    const uint32_t* blj = bl[j >> 1] + (j & 1) * 2;
                    mma16816(accA[i][j], ah[i], bhj);
                    mma16816(accB[i][j], al[i], bhj);
                    mma16816(accB[i][j], ah[i], blj);
                }
        }
        __syncthreads();
    }

    const float INV = 4.8828125e-4f;
    float* dst = g_part + (size_t)((bk * 2 + mt) * 8 + s) * 16384;
#pragma unroll
    for (int i = 0; i < 2; i++)
#pragma unroll
        for (int j = 0; j < 4; j++)
#pragma unroll
            for (int r = 0; r < 4; r++) {
                int o  = mw * 32 + i * 16 + q + (r >> 1) * 8;
                int ii = nw * 32 + j * 8 + tq * 2 + (r & 1);
                dst[(size_t)o * 128 + ii] = accA[i][j][r] + accB[i][j][r] * INV;
            }
}

// =====================================================================
// split-K reduce + softmax (8 splits)
// =====================================================================
__global__ void __launch_bounds__(128) softmax_kernel(float* __restrict__ out)
{
    const int bo = blockIdx.x, b = bo >> 8, o = bo & 255;
    const int mt = o >> 7, ol = o & 127, i = threadIdx.x;
    const float SCALE = 0.029462782549439476f;
    float lg[9];
#pragma unroll
    for (int k = 0; k < 9; k++) {
        const float* p = g_part + (size_t)(((b * 9 + k) * 2 + mt) * 8) * 16384 + (size_t)ol * 128 + i;
        float sum = 0.f;
#pragma unroll
        for (int s = 0; s < 8; s++) sum += p[(size_t)s * 16384];
        lg[k] = sum * SCALE;
    }
    float m = lg[0];
#pragma unroll
    for (int k = 1; k < 9; k++) m = fmaxf(m, lg[k]);
#pragma unroll
    for (int off = 16; off; off >>= 1) m = fmaxf(m, __shfl_xor_sync(0xffffffffu, m, off));
    __shared__ float smax[4];
    if ((i & 31) == 0) smax[i >> 5] = m;
    __syncthreads();
    m = fmaxf(fmaxf(smax[0], smax[1]), fmaxf(smax[2], smax[3]));
    float e[9], ls = 0.f;
#pragma unroll
    for (int k = 0; k < 9; k++) { e[k] = expf(lg[k] - m); ls += e[k]; }
#pragma unroll
    for (int off = 16; off; off >>= 1) ls += __shfl_xor_sync(0xffffffffu, ls, off);
    __shared__ float ssum[4];
    if ((i & 31) == 0) ssum[i >> 5] = ls;
    __syncthreads();
    ls = (ssum[0] + ssum[1]) + (ssum[2] + ssum[3]);
    float inv = 1.f / ls;
    float* dst = out + ((size_t)bo * 128 + i) * 9;
#pragma unroll
    for (int k = 0; k < 9; k++) dst[k] = e[k] * inv;
}

// =====================================================================
extern "C" void kernel_launch(void* const* d_in, const int* in_sizes, int n_in,
                              void* d_out, int out_size)
{
    const float* x  = (const float*)d_in[0];
    const float* w1 = (const float*)d_in[1];
    const float* w2 = (const float*)d_in[2];
    float* out = (float*)d_out;

    cudaFuncSetAttribute(wino_gemm_kernel, cudaFuncAttributeMaxDynamicSharedMemorySize, W_SMEM);
    cudaFuncSetAttribute(gemm2_kernel,     cudaFuncAttributeMaxDynamicSharedMemorySize, G2_SMEM);

    prep_uw_kernel<<<(NCO * CIN + 255) / 256, 256>>>(w1, w2);
    transform_x_kernel<<<dim3(12, 192, 16), 256>>>(x);
    wino_gemm_kernel<<<dim3(NTILE / 32, 3, NB), 256, W_SMEM>>>();
    gemm2_kernel<<<dim3(8, 2, 36), 512, G2_SMEM>>>();
    softmax_kernel<<<NB * COUTB, 128>>>(out);
}

// round 14
// speedup vs baseline: 3.6424x; 1.1505x over previous
#include <cuda_runtime.h>
#include <cuda_fp16.h>
#include <math.h>
#include <stdint.h>

#define CIN   128
#define COUTB 256
#define HW    384
#define LPOS  16384
#define NB    4
#define NTILE 36864            // 192*192 winograd tiles per image
#define NCO   384              // fused couts

// ---------------- static device scratch ----------------
__device__ __align__(16) float  g_part[(size_t)36 * 2 * 8 * 128 * 128];
__device__ __align__(16) __half g_y1h[(size_t)NB * 9 * LPOS * CIN];
__device__ __align__(16) __half g_y1l[(size_t)NB * 9 * LPOS * CIN];
__device__ __align__(16) __half g_y2h[(size_t)NB * 9 * LPOS * COUTB];
__device__ __align__(16) __half g_y2l[(size_t)NB * 9 * LPOS * COUTB];
__device__ __align__(16) __half g_Vh[(size_t)NB * 16 * NTILE * CIN];
__device__ __align__(16) __half g_Vl[(size_t)NB * 16 * NTILE * CIN];
__device__ __align__(16) __half g_Uh[(size_t)16 * NCO * CIN];
__device__ __align__(16) __half g_Ul[(size_t)16 * NCO * CIN];

// ---------------- helpers ----------------
__device__ __forceinline__ uint32_t s2u(const void* p) {
    uint32_t a; asm("{ .reg .u64 t; cvta.to.shared.u64 t, %1; cvt.u32.u64 %0, t; }" : "=r"(a) : "l"(p)); return a;
}
__device__ __forceinline__ void cpa16(uint32_t dst, const void* src) {
    asm volatile("cp.async.cg.shared.global [%0], [%1], 16;" :: "r"(dst), "l"(src));
}
__device__ __forceinline__ void ldm4(uint32_t* r, uint32_t addr) {
    asm volatile("ldmatrix.sync.aligned.m8n8.x4.shared.b16 {%0,%1,%2,%3}, [%4];"
        : "=r"(r[0]), "=r"(r[1]), "=r"(r[2]), "=r"(r[3]) : "r"(addr));
}
__device__ __forceinline__ void ldm4t(uint32_t* r, uint32_t addr) {
    asm volatile("ldmatrix.sync.aligned.m8n8.x4.trans.shared.b16 {%0,%1,%2,%3}, [%4];"
        : "=r"(r[0]), "=r"(r[1]), "=r"(r[2]), "=r"(r[3]) : "r"(addr));
}
__device__ __forceinline__ void mma16816(float* d, const uint32_t* a, const uint32_t* b) {
    asm volatile("mma.sync.aligned.m16n8k16.row.col.f32.f16.f16.f32 "
        "{%0,%1,%2,%3}, {%4,%5,%6,%7}, {%8,%9}, {%0,%1,%2,%3};"
        : "+f"(d[0]), "+f"(d[1]), "+f"(d[2]), "+f"(d[3])
        : "r"(a[0]), "r"(a[1]), "r"(a[2]), "r"(a[3]), "r"(b[0]), "r"(b[1]));
}

// =====================================================================
// K1: weight transform U = G g G^T, fp16 hi + 2048*lo limbs. [e][co][ci]
// =====================================================================
__global__ void prep_uw_kernel(const float* __restrict__ w1, const float* __restrict__ w2)
{
    int idx = blockIdx.x * 256 + threadIdx.x;
    if (idx >= NCO * CIN) return;
    int co = idx >> 7, ci = idx & 127;
    const float* src = (co < CIN) ? (w1 + ((size_t)co * CIN + ci) * 9)
                                  : (w2 + ((size_t)(co - CIN) * CIN + ci) * 9);
    float g[3][3];
#pragma unroll
    for (int r = 0; r < 3; r++)
#pragma unroll
        for (int c = 0; c < 3; c++) g[r][c] = src[r * 3 + c];
    float tr[4][3];
#pragma unroll
    for (int c = 0; c < 3; c++) {
        tr[0][c] = g[0][c];
        tr[1][c] = 0.5f * (g[0][c] + g[1][c] + g[2][c]);
        tr[2][c] = 0.5f * (g[0][c] - g[1][c] + g[2][c]);
        tr[3][c] = g[2][c];
    }
#pragma unroll
    for (int r = 0; r < 4; r++) {
        float uu[4];
        uu[0] = tr[r][0];
        uu[1] = 0.5f * (tr[r][0] + tr[r][1] + tr[r][2]);
        uu[2] = 0.5f * (tr[r][0] - tr[r][1] + tr[r][2]);
        uu[3] = tr[r][2];
#pragma unroll
        for (int c = 0; c < 4; c++) {
            int e = r * 4 + c;
            __half hi = __float2half_rn(uu[c]);
            __half lo = __float2half_rn((uu[c] - __half2float(hi)) * 2048.0f);
            g_Uh[(size_t)e * (NCO * CIN) + idx] = hi;
            g_Ul[(size_t)e * (NCO * CIN) + idx] = lo;
        }
    }
}

// =====================================================================
// K2: input transform V = B^T d B per 4x4 window (stride 2, pad 1).
// =====================================================================
__global__ void transform_x_kernel(const float* __restrict__ x)
{
    __shared__ float st[4][34][33];
    const int bx = blockIdx.x;
    const int ty = blockIdx.y;
    const int cic = blockIdx.z & 3, b = blockIdx.z >> 2;
    const int t = threadIdx.x, l = t & 31, wrp = t >> 5;

#pragma unroll
    for (int it = 0; it < 4; it++) {
        int ci_l = it * 8 + wrp;
        const float* xp = x + ((size_t)(b * CIN + cic * 32 + ci_l)) * HW * HW;
#pragma unroll
        for (int r = 0; r < 4; r++) {
            int h = 2 * ty - 1 + r;
            for (int c = l; c < 34; c += 32) {
                int w = bx * 32 - 1 + c;
                float v = 0.f;
                if ((unsigned)h < HW && (unsigned)w < HW) v = xp[(size_t)h * HW + w];
                st[r][c][ci_l] = v;
            }
        }
    }
    __syncthreads();

    const int ci_l = t & 31, tl = t >> 5;
#pragma unroll
    for (int pass = 0; pass < 2; pass++) {
        int txl = pass * 8 + tl;
        int cb  = 2 * txl;
        float d[4][4];
#pragma unroll
        for (int r = 0; r < 4; r++)
#pragma unroll
            for (int c = 0; c < 4; c++) d[r][c] = st[r][cb + c][ci_l];
        float tm[4][4];
#pragma unroll
        for (int c = 0; c < 4; c++) {
            tm[0][c] = d[0][c] - d[2][c];
            tm[1][c] = d[1][c] + d[2][c];
            tm[2][c] = d[2][c] - d[1][c];
            tm[3][c] = d[1][c] - d[3][c];
        }
        size_t tile = (size_t)ty * 192 + bx * 16 + txl;
#pragma unroll
        for (int r = 0; r < 4; r++) {
            float vv[4];
            vv[0] = tm[r][0] - tm[r][2];
            vv[1] = tm[r][1] + tm[r][2];
            vv[2] = tm[r][2] - tm[r][1];
            vv[3] = tm[r][1] - tm[r][3];
#pragma unroll
            for (int c = 0; c < 4; c++) {
                int e = r * 4 + c;
                size_t off = ((size_t)(b * 16 + e) * NTILE + tile) * CIN + cic * 32 + ci_l;
                __half hi = __float2half_rn(vv[c]);
                g_Vh[off] = hi;
                g_Vl[off] = __float2half_rn((vv[c] - __half2float(hi)) * 2048.0f);
            }
        }
    }
}

// =====================================================================
// K3: winograd GEMM + fused output transform, scatter as half limbs.
// CTA: co 128 x tiles 64, loop e 0..15. 512 thr, 16 warps (4m x 4n),
// warp = 32co x 16tile. Row stride 136 halves.
// =====================================================================
#define W_AH   0                   // halves
#define W_AL   17408               // 128*136
#define W_BH   34816
#define W_BL   43520               // B limb = 64*136 = 8704
#define W_STG  52224               // halves per stage
#define W_SMEM (2 * W_STG * 2)     // 208896 bytes

__global__ void __launch_bounds__(512, 1) wino_gemm_kernel()
{
    extern __shared__ __half sw[];
    const int t = threadIdx.x, l = t & 31, wrp = t >> 5;
    const int mw = wrp & 3, nw = wrp >> 2;
    const int q = l >> 2, tq = l & 3;
    const int tb = blockIdx.x, cob = blockIdx.y, b = blockIdx.z;
    const uint32_t smb = s2u(sw);

    float yac[2][2][4][4];
#pragma unroll
    for (int i = 0; i < 2; i++)
#pragma unroll
        for (int j = 0; j < 2; j++)
#pragma unroll
            for (int d = 0; d < 4; d++)
#pragma unroll
                for (int uv = 0; uv < 4; uv++) yac[i][j][d][uv] = 0.f;

    auto load_e = [&](int e, int buf) {
        const uint32_t base = smb + buf * (W_STG * 2);
        const __half* Uh = g_Uh + (size_t)e * (NCO * CIN) + (size_t)cob * 128 * CIN;
        const __half* Ul = g_Ul + (size_t)e * (NCO * CIN) + (size_t)cob * 128 * CIN;
#pragma unroll
        for (int i = 0; i < 4; i++) {
            int id = t + i * 512;            // 0..2047
            int row = id >> 4, kc = id & 15;
            uint32_t o = (row * 136 + kc * 8) * 2;
            cpa16(base + o,            Uh + (size_t)row * CIN + kc * 8);
            cpa16(base + W_AL * 2 + o, Ul + (size_t)row * CIN + kc * 8);
        }
        const __half* Vh = g_Vh + ((size_t)(b * 16 + e) * NTILE + (size_t)tb * 64) * CIN;
        const __half* Vl = g_Vl + ((size_t)(b * 16 + e) * NTILE + (size_t)tb * 64) * CIN;
#pragma unroll
        for (int i = 0; i < 2; i++) {
            int id = t + i * 512;            // 0..1023
            int row = id >> 4, kc = id & 15;
            uint32_t o = (row * 136 + kc * 8) * 2;
            cpa16(base + W_BH * 2 + o, Vh + (size_t)row * CIN + kc * 8);
            cpa16(base + W_BL * 2 + o, Vl + (size_t)row * CIN + kc * 8);
        }
        asm volatile("cp.async.commit_group;" ::: "memory");
    };

    const float AT0[4] = {1.f, 1.f, 1.f, 0.f};
    const float AT1[4] = {0.f, 1.f, -1.f, -1.f};
    const float INV = 4.8828125e-4f;

    load_e(0, 0);

#pragma unroll 1
    for (int e = 0; e < 16; e++) {
        const int buf = e & 1;
        if (e < 15) {
            load_e(e + 1, buf ^ 1);
            asm volatile("cp.async.wait_group 1;" ::: "memory");
        } else {
            asm volatile("cp.async.wait_group 0;" ::: "memory");
        }
        __syncthreads();

        const uint32_t base = smb + buf * (W_STG * 2);
        const int r8 = l & 7, tt = l >> 3;

        float mA[2][2][4], mB[2][2][4];
#pragma unroll
        for (int i = 0; i < 2; i++)
#pragma unroll
            for (int j = 0; j < 2; j++)
#pragma unroll
                for (int d = 0; d < 4; d++) { mA[i][j][d] = 0.f; mB[i][j][d] = 0.f; }

#pragma unroll
        for (int ks = 0; ks < 8; ks++) {
            uint32_t ah[2][4], al[2][4];
#pragma unroll
            for (int i = 0; i < 2; i++) {
                uint32_t arow = mw * 32 + i * 16 + (tt & 1) * 8 + r8;
                uint32_t aoff = arow * 272 + (ks * 16 + (tt >> 1) * 8) * 2;
                ldm4(ah[i], base + aoff);
                ldm4(al[i], base + W_AL * 2 + aoff);
            }
            uint32_t bh4[4], bl4[4];
            {
                uint32_t brow = nw * 16 + (tt >> 1) * 8 + r8;
                uint32_t boff = brow * 272 + (ks * 16 + (tt & 1) * 8) * 2;
                ldm4(bh4, base + W_BH * 2 + boff);
                ldm4(bl4, base + W_BL * 2 + boff);
            }
#pragma unroll
            for (int i = 0; i < 2; i++)
#pragma unroll
                for (int j = 0; j < 2; j++) {
                    mma16816(mA[i][j], ah[i], bh4 + j * 2);
                    mma16816(mB[i][j], al[i], bh4 + j * 2);
                    mma16816(mB[i][j], ah[i], bl4 + j * 2);
                }
        }

        const int er = e >> 2, ec = e & 3;
        const float u0 = AT0[er], u1 = AT1[er], v0 = AT0[ec], v1 = AT1[ec];
#pragma unroll
        for (int i = 0; i < 2; i++)
#pragma unroll
            for (int j = 0; j < 2; j++)
#pragma unroll
                for (int d = 0; d < 4; d++) {
                    float m = mA[i][j][d] + mB[i][j][d] * INV;
                    yac[i][j][d][0] += u0 * v0 * m;
                    yac[i][j][d][1] += u0 * v1 * m;
                    yac[i][j][d][2] += u1 * v0 * m;
                    yac[i][j][d][3] += u1 * v1 * m;
                }
        __syncthreads();
    }

    // ---- scatter into bin layout as fp16 hi/lo limbs ----
#pragma unroll
    for (int i = 0; i < 2; i++) {
#pragma unroll
        for (int j = 0; j < 2; j++) {
#pragma unroll
            for (int d = 0; d < 4; d++) {
                int co = cob * 128 + mw * 32 + i * 16 + (d >> 1) * 8 + q;
                int tile = tb * 64 + nw * 16 + j * 8 + tq * 2 + (d & 1);
                int tyy = tile / 192, txx = tile - tyy * 192;
#pragma unroll
                for (int u = 0; u < 2; u++) {
#pragma unroll
                    for (int v = 0; v < 2; v++) {
                        int h = 2 * tyy + u, w = 2 * txx + v;
                        int k = (h % 3) * 3 + (w % 3);
                        size_t p   = (size_t)(h / 3) * 128 + (w / 3);
                        size_t row = (size_t)(b * 9 + k) * LPOS + p;
                        float val = yac[i][j][d][u * 2 + v];
                        __half hi = __float2half_rn(val);
                        __half lo = __float2half_rn((val - __half2float(hi)) * 2048.0f);
                        if (co < CIN) {
                            g_y1h[row * CIN + co] = hi;
                            g_y1l[row * CIN + co] = lo;
                        } else {
                            g_y2h[row * COUTB + co - CIN] = hi;
                            g_y2l[row * COUTB + co - CIN] = lo;
                        }
                    }
                }
            }
        }
    }
}

// =====================================================================
// stage 2: bin GEMM on split-FP16 mma (proven R12). K=16384 split 8.
// =====================================================================
#define G2_AL  4352                // halves: 32*136
#define G2_BH  8704
#define G2_BL  13056
#define G2_STG 17408
#define G2_SMEM (2 * G2_STG * 2)   // 69632 bytes

__global__ void __launch_bounds__(512) gemm2_kernel()
{
    extern __shared__ __half s2[];
    const int t = threadIdx.x, l = t & 31, wrp = t >> 5;
    const int mw = wrp & 3, nw = wrp >> 2;
    const int q = l >> 2, tq = l & 3;
    const int s = blockIdx.x, mt = blockIdx.y, bk = blockIdx.z;
    const uint32_t smb = s2u(s2);

    const __half* __restrict__ Ah = g_y2h + (size_t)bk * LPOS * COUTB + mt * 128;
    const __half* __restrict__ Al = g_y2l + (size_t)bk * LPOS * COUTB + mt * 128;
    const __half* __restrict__ Bh = g_y1h + (size_t)bk * LPOS * CIN;
    const __half* __restrict__ Bl = g_y1l + (size_t)bk * LPOS * CIN;

    float accA[2][4][4], accB[2][4][4];
#pragma unroll
    for (int i = 0; i < 2; i++)
#pragma unroll
        for (int j = 0; j < 4; j++)
#pragma unroll
            for (int r = 0; r < 4; r++) { accA[i][j][r] = 0.f; accB[i][j][r] = 0.f; }

    const int row = t >> 4, kc = t & 15;
    const uint32_t so = (row * 136 + kc * 8) * 2;

    auto load_chunk = [&](int p0, int buf) {
        const uint32_t base = smb + buf * (G2_STG * 2);
        size_t ga = (size_t)(p0 + row) * COUTB + kc * 8;
        size_t gb = (size_t)(p0 + row) * CIN + kc * 8;
        cpa16(base + so,             Ah + ga);
        cpa16(base + G2_AL * 2 + so, Al + ga);
        cpa16(base + G2_BH * 2 + so, Bh + gb);
        cpa16(base + G2_BL * 2 + so, Bl + gb);
        asm volatile("cp.async.commit_group;" ::: "memory");
    };

    const int pBase = s * (LPOS / 8);
    load_chunk(pBase, 0);

    for (int pc = 0; pc < 64; pc++) {
        const int buf = pc & 1;
        if (pc < 63) {
            load_chunk(pBase + (pc + 1) * 32, buf ^ 1);
            asm volatile("cp.async.wait_group 1;" ::: "memory");
        } else {
            asm volatile("cp.async.wait_group 0;" ::: "memory");
        }
        __syncthreads();

        const uint32_t base = smb + buf * (G2_STG * 2);
        const int r8 = l & 7, g = l >> 3;

#pragma unroll
        for (int ks = 0; ks < 2; ks++) {
            uint32_t ah[2][4], al[2][4];
#pragma unroll
            for (int i = 0; i < 2; i++) {
                uint32_t aoff = ((ks * 16 + (g >> 1) * 8 + r8) * 136
                               + mw * 32 + i * 16 + (g & 1) * 8) * 2;
                ldm4t(ah[i], base + aoff);
                ldm4t(al[i], base + G2_AL * 2 + aoff);
            }
            uint32_t bh[2][4], bl[2][4];
#pragma unroll
            for (int jp = 0; jp < 2; jp++) {
                uint32_t boff = ((ks * 16 + (g & 1) * 8 + r8) * 136
                               + nw * 32 + jp * 16 + (g >> 1) * 8) * 2;
                ldm4t(bh[jp], base + G2_BH * 2 + boff);
                ldm4t(bl[jp], base + G2_BL * 2 + boff);
            }
#pragma unroll
            for (int i = 0; i < 2; i++)
#pragma unroll
                for (int j = 0; j < 4; j++) {
                    const uint32_t* bhj = bh[j >> 1] + (j & 1) * 2;
                    const uint32_t* blj = bl[j >> 1] + (j & 1) * 2;
                    mma16816(accA[i][j], ah[i], bhj);
                    mma16816(accB[i][j], al[i], bhj);
                    mma16816(accB[i][j], ah[i], blj);
                }
        }
        __syncthreads();
    }

    const float INV = 4.8828125e-4f;
    float* dst = g_part + (size_t)((bk * 2 + mt) * 8 + s) * 16384;
#pragma unroll
    for (int i = 0; i < 2; i++)
#pragma unroll
        for (int j = 0; j < 4; j++)
#pragma unroll
            for (int r = 0; r < 4; r++) {
                int o  = mw * 32 + i * 16 + q + (r >> 1) * 8;
                int ii = nw * 32 + j * 8 + tq * 2 + (r & 1);
                dst[(size_t)o * 128 + ii] = accA[i][j][r] + accB[i][j][r] * INV;
            }
}

// =====================================================================
// split-K reduce + softmax (8 splits)
// =====================================================================
__global__ void __launch_bounds__(128) softmax_kernel(float* __restrict__ out)
{
    const int bo = blockIdx.x, b = bo >> 8, o = bo & 255;
    const int mt = o >> 7, ol = o & 127, i = threadIdx.x;
    const float SCALE = 0.029462782549439476f;
    float lg[9];
#pragma unroll
    for (int k = 0; k < 9; k++) {
        const float* p = g_part + (size_t)(((b * 9 + k) * 2 + mt) * 8) * 16384 + (size_t)ol * 128 + i;
        float sum = 0.f;
#pragma unroll
        for (int s = 0; s < 8; s++) sum += p[(size_t)s * 16384];
        lg[k] = sum * SCALE;
    }
    float m = lg[0];
#pragma unroll
    for (int k = 1; k < 9; k++) m = fmaxf(m, lg[k]);
#pragma unroll
    for (int off = 16; off; off >>= 1) m = fmaxf(m, __shfl_xor_sync(0xffffffffu, m, off));
    __shared__ float smax[4];
    if ((i & 31) == 0) smax[i >> 5] = m;
    __syncthreads();
    m = fmaxf(fmaxf(smax[0], smax[1]), fmaxf(smax[2], smax[3]));
    float e[9], ls = 0.f;
#pragma unroll
    for (int k = 0; k < 9; k++) { e[k] = expf(lg[k] - m); ls += e[k]; }
#pragma unroll
    for (int off = 16; off; off >>= 1) ls += __shfl_xor_sync(0xffffffffu, ls, off);
    __shared__ float ssum[4];
    if ((i & 31) == 0) ssum[i >> 5] = ls;
    __syncthreads();
    ls = (ssum[0] + ssum[1]) + (ssum[2] + ssum[3]);
    float inv = 1.f / ls;
    float* dst = out + ((size_t)bo * 128 + i) * 9;
#pragma unroll
    for (int k = 0; k < 9; k++) dst[k] = e[k] * inv;
}

// =====================================================================
extern "C" void kernel_launch(void* const* d_in, const int* in_sizes, int n_in,
                              void* d_out, int out_size)
{
    const float* x  = (const float*)d_in[0];
    const float* w1 = (const float*)d_in[1];
    const float* w2 = (const float*)d_in[2];
    float* out = (float*)d_out;

    cudaFuncSetAttribute(wino_gemm_kernel, cudaFuncAttributeMaxDynamicSharedMemorySize, W_SMEM);
    cudaFuncSetAttribute(gemm2_kernel,     cudaFuncAttributeMaxDynamicSharedMemorySize, G2_SMEM);

    prep_uw_kernel<<<(NCO * CIN + 255) / 256, 256>>>(w1, w2);
    transform_x_kernel<<<dim3(12, 192, 16), 256>>>(x);
    wino_gemm_kernel<<<dim3(NTILE / 64, 3, NB), 512, W_SMEM>>>();
    gemm2_kernel<<<dim3(8, 2, 36), 512, G2_SMEM>>>();
    softmax_kernel<<<NB * COUTB, 128>>>(out);
}

// round 15
// speedup vs baseline: 3.7768x; 1.0369x over previous
#include <cuda_runtime.h>
#include <cuda_fp16.h>
#include <math.h>
#include <stdint.h>

#define CIN   128
#define COUTB 256
#define HW    384
#define LPOS  16384
#define NB    4
#define NTILE 36864            // 192*192 winograd tiles per image
#define NCO   384              // fused couts

// ---------------- static device scratch ----------------
__device__ __align__(16) float  g_part[(size_t)36 * 2 * 8 * 128 * 128];
__device__ __align__(16) __half g_y1h[(size_t)NB * 9 * LPOS * CIN];
__device__ __align__(16) __half g_y1l[(size_t)NB * 9 * LPOS * CIN];
__device__ __align__(16) __half g_y2h[(size_t)NB * 9 * LPOS * COUTB];
__device__ __align__(16) __half g_y2l[(size_t)NB * 9 * LPOS * COUTB];
__device__ __align__(16) __half g_Vh[(size_t)NB * 16 * NTILE * CIN];
__device__ __align__(16) __half g_Vl[(size_t)NB * 16 * NTILE * CIN];
__device__ __align__(16) __half g_Uh[(size_t)16 * NCO * CIN];
__device__ __align__(16) __half g_Ul[(size_t)16 * NCO * CIN];

// ---------------- helpers ----------------
__device__ __forceinline__ uint32_t s2u(const void* p) {
    uint32_t a; asm("{ .reg .u64 t; cvta.to.shared.u64 t, %1; cvt.u32.u64 %0, t; }" : "=r"(a) : "l"(p)); return a;
}
__device__ __forceinline__ void cpa16(uint32_t dst, const void* src) {
    asm volatile("cp.async.cg.shared.global [%0], [%1], 16;" :: "r"(dst), "l"(src));
}
__device__ __forceinline__ void ldm4(uint32_t* r, uint32_t addr) {
    asm volatile("ldmatrix.sync.aligned.m8n8.x4.shared.b16 {%0,%1,%2,%3}, [%4];"
        : "=r"(r[0]), "=r"(r[1]), "=r"(r[2]), "=r"(r[3]) : "r"(addr));
}
__device__ __forceinline__ void ldm4t(uint32_t* r, uint32_t addr) {
    asm volatile("ldmatrix.sync.aligned.m8n8.x4.trans.shared.b16 {%0,%1,%2,%3}, [%4];"
        : "=r"(r[0]), "=r"(r[1]), "=r"(r[2]), "=r"(r[3]) : "r"(addr));
}
__device__ __forceinline__ void mma16816(float* d, const uint32_t* a, const uint32_t* b) {
    asm volatile("mma.sync.aligned.m16n8k16.row.col.f32.f16.f16.f32 "
        "{%0,%1,%2,%3}, {%4,%5,%6,%7}, {%8,%9}, {%0,%1,%2,%3};"
        : "+f"(d[0]), "+f"(d[1]), "+f"(d[2]), "+f"(d[3])
        : "r"(a[0]), "r"(a[1]), "r"(a[2]), "r"(a[3]), "r"(b[0]), "r"(b[1]));
}

// =====================================================================
// K1: weight transform U = G g G^T, fp16 hi + UNSCALED lo limbs. [e][co][ci]
// =====================================================================
__global__ void prep_uw_kernel(const float* __restrict__ w1, const float* __restrict__ w2)
{
    int idx = blockIdx.x * 256 + threadIdx.x;
    if (idx >= NCO * CIN) return;
    int co = idx >> 7, ci = idx & 127;
    const float* src = (co < CIN) ? (w1 + ((size_t)co * CIN + ci) * 9)
                                  : (w2 + ((size_t)(co - CIN) * CIN + ci) * 9);
    float g[3][3];
#pragma unroll
    for (int r = 0; r < 3; r++)
#pragma unroll
        for (int c = 0; c < 3; c++) g[r][c] = src[r * 3 + c];
    float tr[4][3];
#pragma unroll
    for (int c = 0; c < 3; c++) {
        tr[0][c] = g[0][c];
        tr[1][c] = 0.5f * (g[0][c] + g[1][c] + g[2][c]);
        tr[2][c] = 0.5f * (g[0][c] - g[1][c] + g[2][c]);
        tr[3][c] = g[2][c];
    }
#pragma unroll
    for (int r = 0; r < 4; r++) {
        float uu[4];
        uu[0] = tr[r][0];
        uu[1] = 0.5f * (tr[r][0] + tr[r][1] + tr[r][2]);
        uu[2] = 0.5f * (tr[r][0] - tr[r][1] + tr[r][2]);
        uu[3] = tr[r][2];
#pragma unroll
        for (int c = 0; c < 4; c++) {
            int e = r * 4 + c;
            __half hi = __float2half_rn(uu[c]);
            g_Uh[(size_t)e * (NCO * CIN) + idx] = hi;
            g_Ul[(size_t)e * (NCO * CIN) + idx] = __float2half_rn(uu[c] - __half2float(hi));
        }
    }
}

// =====================================================================
// K2: input transform V = B^T d B per 4x4 window (stride 2, pad 1).
// =====================================================================
__global__ void transform_x_kernel(const float* __restrict__ x)
{
    __shared__ float st[4][34][33];
    const int bx = blockIdx.x;
    const int ty = blockIdx.y;
    const int cic = blockIdx.z & 3, b = blockIdx.z >> 2;
    const int t = threadIdx.x, l = t & 31, wrp = t >> 5;

#pragma unroll
    for (int it = 0; it < 4; it++) {
        int ci_l = it * 8 + wrp;
        const float* xp = x + ((size_t)(b * CIN + cic * 32 + ci_l)) * HW * HW;
#pragma unroll
        for (int r = 0; r < 4; r++) {
            int h = 2 * ty - 1 + r;
            for (int c = l; c < 34; c += 32) {
                int w = bx * 32 - 1 + c;
                float v = 0.f;
                if ((unsigned)h < HW && (unsigned)w < HW) v = xp[(size_t)h * HW + w];
                st[r][c][ci_l] = v;
            }
        }
    }
    __syncthreads();

    const int ci_l = t & 31, tl = t >> 5;
#pragma unroll
    for (int pass = 0; pass < 2; pass++) {
        int txl = pass * 8 + tl;
        int cb  = 2 * txl;
        float d[4][4];
#pragma unroll
        for (int r = 0; r < 4; r++)
#pragma unroll
            for (int c = 0; c < 4; c++) d[r][c] = st[r][cb + c][ci_l];
        float tm[4][4];
#pragma unroll
        for (int c = 0; c < 4; c++) {
            tm[0][c] = d[0][c] - d[2][c];
            tm[1][c] = d[1][c] + d[2][c];
            tm[2][c] = d[2][c] - d[1][c];
            tm[3][c] = d[1][c] - d[3][c];
        }
        size_t tile = (size_t)ty * 192 + bx * 16 + txl;
#pragma unroll
        for (int r = 0; r < 4; r++) {
            float vv[4];
            vv[0] = tm[r][0] - tm[r][2];
            vv[1] = tm[r][1] + tm[r][2];
            vv[2] = tm[r][2] - tm[r][1];
            vv[3] = tm[r][1] - tm[r][3];
#pragma unroll
            for (int c = 0; c < 4; c++) {
                int e = r * 4 + c;
                size_t off = ((size_t)(b * 16 + e) * NTILE + tile) * CIN + cic * 32 + ci_l;
                __half hi = __float2half_rn(vv[c]);
                g_Vh[off] = hi;
                g_Vl[off] = __float2half_rn(vv[c] - __half2float(hi));
            }
        }
    }
}

// =====================================================================
// K3: winograd GEMM + fused output transform; single fp32 accumulator
// (unscaled lo limbs -> all 3 products at true scale).
// CTA: co 128 x tiles 64, loop e 0..15. 512 thr, 16 warps (4m x 4n).
// =====================================================================
#define W_AL   17408               // halves: 128*136
#define W_BH   34816
#define W_BL   43520
#define W_STG  52224
#define W_SMEM (2 * W_STG * 2)     // 208896 bytes

__global__ void __launch_bounds__(512, 1) wino_gemm_kernel()
{
    extern __shared__ __half sw[];
    const int t = threadIdx.x, l = t & 31, wrp = t >> 5;
    const int mw = wrp & 3, nw = wrp >> 2;
    const int q = l >> 2, tq = l & 3;
    const int tb = blockIdx.x, cob = blockIdx.y, b = blockIdx.z;
    const uint32_t smb = s2u(sw);

    float yac[2][2][4][4];
#pragma unroll
    for (int i = 0; i < 2; i++)
#pragma unroll
        for (int j = 0; j < 2; j++)
#pragma unroll
            for (int d = 0; d < 4; d++)
#pragma unroll
                for (int uv = 0; uv < 4; uv++) yac[i][j][d][uv] = 0.f;

    auto load_e = [&](int e, int buf) {
        const uint32_t base = smb + buf * (W_STG * 2);
        const __half* Uh = g_Uh + (size_t)e * (NCO * CIN) + (size_t)cob * 128 * CIN;
        const __half* Ul = g_Ul + (size_t)e * (NCO * CIN) + (size_t)cob * 128 * CIN;
#pragma unroll
        for (int i = 0; i < 4; i++) {
            int id = t + i * 512;
            int row = id >> 4, kc = id & 15;
            uint32_t o = (row * 136 + kc * 8) * 2;
            cpa16(base + o,            Uh + (size_t)row * CIN + kc * 8);
            cpa16(base + W_AL * 2 + o, Ul + (size_t)row * CIN + kc * 8);
        }
        const __half* Vh = g_Vh + ((size_t)(b * 16 + e) * NTILE + (size_t)tb * 64) * CIN;
        const __half* Vl = g_Vl + ((size_t)(b * 16 + e) * NTILE + (size_t)tb * 64) * CIN;
#pragma unroll
        for (int i = 0; i < 2; i++) {
            int id = t + i * 512;
            int row = id >> 4, kc = id & 15;
            uint32_t o = (row * 136 + kc * 8) * 2;
            cpa16(base + W_BH * 2 + o, Vh + (size_t)row * CIN + kc * 8);
            cpa16(base + W_BL * 2 + o, Vl + (size_t)row * CIN + kc * 8);
        }
        asm volatile("cp.async.commit_group;" ::: "memory");
    };

    const float AT0[4] = {1.f, 1.f, 1.f, 0.f};
    const float AT1[4] = {0.f, 1.f, -1.f, -1.f};

    load_e(0, 0);

#pragma unroll 1
    for (int e = 0; e < 16; e++) {
        const int buf = e & 1;
        if (e < 15) {
            load_e(e + 1, buf ^ 1);
            asm volatile("cp.async.wait_group 1;" ::: "memory");
        } else {
            asm volatile("cp.async.wait_group 0;" ::: "memory");
        }
        __syncthreads();

        const uint32_t base = smb + buf * (W_STG * 2);
        const int r8 = l & 7, tt = l >> 3;

        float m_[2][2][4];
#pragma unroll
        for (int i = 0; i < 2; i++)
#pragma unroll
            for (int j = 0; j < 2; j++)
#pragma unroll
                for (int d = 0; d < 4; d++) m_[i][j][d] = 0.f;

#pragma unroll
        for (int ks = 0; ks < 8; ks++) {
            uint32_t ah[2][4], al[2][4];
#pragma unroll
            for (int i = 0; i < 2; i++) {
                uint32_t arow = mw * 32 + i * 16 + (tt & 1) * 8 + r8;
                uint32_t aoff = arow * 272 + (ks * 16 + (tt >> 1) * 8) * 2;
                ldm4(ah[i], base + aoff);
                ldm4(al[i], base + W_AL * 2 + aoff);
            }
            uint32_t bh4[4], bl4[4];
            {
                uint32_t brow = nw * 16 + (tt >> 1) * 8 + r8;
                uint32_t boff = brow * 272 + (ks * 16 + (tt & 1) * 8) * 2;
                ldm4(bh4, base + W_BH * 2 + boff);
                ldm4(bl4, base + W_BL * 2 + boff);
            }
#pragma unroll
            for (int i = 0; i < 2; i++)
#pragma unroll
                for (int j = 0; j < 2; j++) {
                    mma16816(m_[i][j], ah[i], bh4 + j * 2);   // hi*hi
                    mma16816(m_[i][j], al[i], bh4 + j * 2);   // lo*hi (true scale)
                    mma16816(m_[i][j], ah[i], bl4 + j * 2);   // hi*lo (true scale)
                }
        }

        const int er = e >> 2, ec = e & 3;
        const float u0 = AT0[er], u1 = AT1[er], v0 = AT0[ec], v1 = AT1[ec];
#pragma unroll
        for (int i = 0; i < 2; i++)
#pragma unroll
            for (int j = 0; j < 2; j++)
#pragma unroll
                for (int d = 0; d < 4; d++) {
                    float m = m_[i][j][d];
                    yac[i][j][d][0] += u0 * v0 * m;
                    yac[i][j][d][1] += u0 * v1 * m;
                    yac[i][j][d][2] += u1 * v0 * m;
                    yac[i][j][d][3] += u1 * v1 * m;
                }
        __syncthreads();
    }

    // ---- scatter into bin layout as fp16 hi/lo limbs (lo unscaled) ----
#pragma unroll
    for (int i = 0; i < 2; i++) {
#pragma unroll
        for (int j = 0; j < 2; j++) {
#pragma unroll
            for (int d = 0; d < 4; d++) {
                int co = cob * 128 + mw * 32 + i * 16 + (d >> 1) * 8 + q;
                int tile = tb * 64 + nw * 16 + j * 8 + tq * 2 + (d & 1);
                int tyy = tile / 192, txx = tile - tyy * 192;
#pragma unroll
                for (int u = 0; u < 2; u++) {
#pragma unroll
                    for (int v = 0; v < 2; v++) {
                        int h = 2 * tyy + u, w = 2 * txx + v;
                        int k = (h % 3) * 3 + (w % 3);
                        size_t p   = (size_t)(h / 3) * 128 + (w / 3);
                        size_t row = (size_t)(b * 9 + k) * LPOS + p;
                        float val = yac[i][j][d][u * 2 + v];
                        __half hi = __float2half_rn(val);
                        __half lo = __float2half_rn(val - __half2float(hi));
                        if (co < CIN) {
                            g_y1h[row * CIN + co] = hi;
                            g_y1l[row * CIN + co] = lo;
                        } else {
                            g_y2h[row * COUTB + co - CIN] = hi;
                            g_y2l[row * COUTB + co - CIN] = lo;
                        }
                    }
                }
            }
        }
    }
}

// =====================================================================
// stage 2: bin GEMM, single-acc split-FP16. CTA 128o x 64i, 256 thr,
// 8 warps (4m x 2n, warp 32x32), 2 CTAs/SM. K=16384 split 8.
// grid (8 splits, mt*2+nt (4), 36 bins)
// =====================================================================
#define G2_AH  0                    // halves: A 32*136 per limb
#define G2_AL  4352
#define G2_BH  8704                 // B 32*72 per limb
#define G2_BL  11008
#define G2_STG 13312
#define G2_SMEM (2 * G2_STG * 2)    // 53248 bytes

__global__ void __launch_bounds__(256, 2) gemm2_kernel()
{
    extern __shared__ __half s2[];
    const int t = threadIdx.x, l = t & 31, wrp = t >> 5;
    const int mw = wrp & 3, nw = wrp >> 2;          // 4m x 2n
    const int q = l >> 2, tq = l & 3;
    const int s = blockIdx.x;
    const int mt = blockIdx.y >> 1, nt = blockIdx.y & 1;
    const int bk = blockIdx.z;
    const uint32_t smb = s2u(s2);

    const __half* __restrict__ Ah = g_y2h + (size_t)bk * LPOS * COUTB + mt * 128;
    const __half* __restrict__ Al = g_y2l + (size_t)bk * LPOS * COUTB + mt * 128;
    const __half* __restrict__ Bh = g_y1h + (size_t)bk * LPOS * CIN + nt * 64;
    const __half* __restrict__ Bl = g_y1l + (size_t)bk * LPOS * CIN + nt * 64;

    float acc[2][4][4];
#pragma unroll
    for (int i = 0; i < 2; i++)
#pragma unroll
        for (int j = 0; j < 4; j++)
#pragma unroll
            for (int r = 0; r < 4; r++) acc[i][j][r] = 0.f;

    // A: 32 rows x 16 chunks of 8 halves (1024 cpa per limb) -> 4/thread
    // B: 32 rows x 8 chunks                                  -> 1/thread (256)
    const int arow = t >> 3, akc = t & 7;       // covers 32x8? no: 256 thr = 32x8
    auto load_chunk = [&](int p0, int buf) {
        const uint32_t base = smb + buf * (G2_STG * 2);
#pragma unroll
        for (int i = 0; i < 2; i++) {
            int id = t + i * 256;               // 0..511 -> row=id>>4, kc=id&15
            int row = id >> 4, kc = id & 15;
            uint32_t o = (row * 136 + kc * 8) * 2;
            size_t ga = (size_t)(p0 + row) * COUTB + kc * 8;
            cpa16(base + o,            Ah + ga);
            cpa16(base + G2_AL * 2 + o, Al + ga);
        }
        {
            int row = t >> 3, kc = t & 7;       // 32 rows x 8 chunks
            uint32_t o = (row * 72 + kc * 8) * 2;
            size_t gb = (size_t)(p0 + row) * CIN + kc * 8;
            cpa16(base + G2_BH * 2 + o, Bh + gb);
            cpa16(base + G2_BL * 2 + o, Bl + gb);
        }
        asm volatile("cp.async.commit_group;" ::: "memory");
    };

    const int pBase = s * (LPOS / 8);
    load_chunk(pBase, 0);

    for (int pc = 0; pc < 64; pc++) {
        const int buf = pc & 1;
        if (pc < 63) {
            load_chunk(pBase + (pc + 1) * 32, buf ^ 1);
            asm volatile("cp.async.wait_group 1;" ::: "memory");
        } else {
            asm volatile("cp.async.wait_group 0;" ::: "memory");
        }
        __syncthreads();

        const uint32_t base = smb + buf * (G2_STG * 2);
        const int r8 = l & 7, g = l >> 3;

#pragma unroll
        for (int ks = 0; ks < 2; ks++) {
            // A frags (trans): k rows x o cols, stride 136
            uint32_t ah[2][4], al[2][4];
#pragma unroll
            for (int i = 0; i < 2; i++) {
                uint32_t aoff = ((ks * 16 + (g >> 1) * 8 + r8) * 136
                               + mw * 32 + i * 16 + (g & 1) * 8) * 2;
                ldm4t(ah[i], base + aoff);
                ldm4t(al[i], base + G2_AL * 2 + aoff);
            }
            // B frags (trans): k rows x i cols, stride 72; jp covers 16 i
            uint32_t bh[2][4], bl[2][4];
#pragma unroll
            for (int jp = 0; jp < 2; jp++) {
                uint32_t boff = ((ks * 16 + (g & 1) * 8 + r8) * 72
                               + nw * 32 + jp * 16 + (g >> 1) * 8) * 2;
                ldm4t(bh[jp], base + G2_BH * 2 + boff);
                ldm4t(bl[jp], base + G2_BL * 2 + boff);
            }
#pragma unroll
            for (int i = 0; i < 2; i++)
#pragma unroll
                for (int j = 0; j < 4; j++) {
                    const uint32_t* bhj = bh[j >> 1] + (j & 1) * 2;
                    const uint32_t* blj = bl[j >> 1] + (j & 1) * 2;
                    mma16816(acc[i][j], ah[i], bhj);
                    mma16816(acc[i][j], al[i], bhj);
                    mma16816(acc[i][j], ah[i], blj);
                }
        }
        __syncthreads();
    }

    float* dst = g_part + (size_t)((bk * 2 + mt) * 8 + s) * 16384;
#pragma unroll
    for (int i = 0; i < 2; i++)
#pragma unroll
        for (int j = 0; j < 4; j++)
#pragma unroll
            for (int r = 0; r < 4; r++) {
                int o  = mw * 32 + i * 16 + q + (r >> 1) * 8;
                int ii = nt * 64 + nw * 32 + j * 8 + tq * 2 + (r & 1);
                dst[(size_t)o * 128 + ii] = acc[i][j][r];
            }
}

// =====================================================================
// split-K reduce + softmax (8 splits)
// =====================================================================
__global__ void __launch_bounds__(128) softmax_kernel(float* __restrict__ out)
{
    const int bo = blockIdx.x, b = bo >> 8, o = bo & 255;
    const int mt = o >> 7, ol = o & 127, i = threadIdx.x;
    const float SCALE = 0.029462782549439476f;
    float lg[9];
#pragma unroll
    for (int k = 0; k < 9; k++) {
        const float* p = g_part + (size_t)(((b * 9 + k) * 2 + mt) * 8) * 16384 + (size_t)ol * 128 + i;
        float sum = 0.f;
#pragma unroll
        for (int s = 0; s < 8; s++) sum += p[(size_t)s * 16384];
        lg[k] = sum * SCALE;
    }
    float m = lg[0];
#pragma unroll
    for (int k = 1; k < 9; k++) m = fmaxf(m, lg[k]);
#pragma unroll
    for (int off = 16; off; off >>= 1) m = fmaxf(m, __shfl_xor_sync(0xffffffffu, m, off));
    __shared__ float smax[4];
    if ((i & 31) == 0) smax[i >> 5] = m;
    __syncthreads();
    m = fmaxf(fmaxf(smax[0], smax[1]), fmaxf(smax[2], smax[3]));
    float e[9], ls = 0.f;
#pragma unroll
    for (int k = 0; k < 9; k++) { e[k] = expf(lg[k] - m); ls += e[k]; }
#pragma unroll
    for (int off = 16; off; off >>= 1) ls += __shfl_xor_sync(0xffffffffu, ls, off);
    __shared__ float ssum[4];
    if ((i & 31) == 0) ssum[i >> 5] = ls;
    __syncthreads();
    ls = (ssum[0] + ssum[1]) + (ssum[2] + ssum[3]);
    float inv = 1.f / ls;
    float* dst = out + ((size_t)bo * 128 + i) * 9;
#pragma unroll
    for (int k = 0; k < 9; k++) dst[k] = e[k] * inv;
}

// =====================================================================
extern "C" void kernel_launch(void* const* d_in, const int* in_sizes, int n_in,
                              void* d_out, int out_size)
{
    const float* x  = (const float*)d_in[0];
    const float* w1 = (const float*)d_in[1];
    const float* w2 = (const float*)d_in[2];
    float* out = (float*)d_out;

    cudaFuncSetAttribute(wino_gemm_kernel, cudaFuncAttributeMaxDynamicSharedMemorySize, W_SMEM);
    cudaFuncSetAttribute(gemm2_kernel,     cudaFuncAttributeMaxDynamicSharedMemorySize, G2_SMEM);

    prep_uw_kernel<<<(NCO * CIN + 255) / 256, 256>>>(w1, w2);
    transform_x_kernel<<<dim3(12, 192, 16), 256>>>(x);
    wino_gemm_kernel<<<dim3(NTILE / 64, 3, NB), 512, W_SMEM>>>();
    gemm2_kernel<<<dim3(8, 4, 36), 256, G2_SMEM>>>();
    softmax_kernel<<<NB * COUTB, 128>>>(out);
}